// round 2
// baseline (speedup 1.0000x reference)
#include <cuda_runtime.h>
#include <cuda_bf16.h>
#include <math.h>

// ---------------- problem constants ----------------
#define BB 2
#define SS 512
#define CC 512
#define LL 1024
#define HH 1024
#define NHEAD 16
#define HD 64
#define FF 4096
#define NLAYER 4
#define VV 32000
#define TDIM 512
#define NEGINF (-1000000000.0f)

// ---------------- scratch (device globals; no allocs allowed) ----------------
__device__ float g_x  [BB*LL*HH];
__device__ float g_xn [BB*LL*HH];
__device__ float g_q  [BB*LL*HH];
__device__ float g_k  [BB*LL*HH];
__device__ float g_v  [BB*LL*HH];
__device__ float g_att[BB*LL*HH];
__device__ float g_m1 [BB*LL*FF];
__device__ float g_m2 [BB*LL*FF];
__device__ float g_xc [BB*SS*(HH+TDIM)];
__device__ float g_h1 [BB*SS*HH];
__device__ float g_hr [BB*SS*TDIM];
__device__ unsigned char g_pad[BB*LL];

// ---------------- block reductions ----------------
__device__ __forceinline__ float block_reduce_sum(float v, float* red) {
    int t = threadIdx.x, lane = t & 31, w = t >> 5;
    #pragma unroll
    for (int o = 16; o > 0; o >>= 1) v += __shfl_xor_sync(0xffffffffu, v, o);
    if (lane == 0) red[w] = v;
    __syncthreads();
    int nw = (blockDim.x + 31) >> 5;
    float r = (t < nw) ? red[t] : 0.f;
    if (w == 0) {
        #pragma unroll
        for (int o = 16; o > 0; o >>= 1) r += __shfl_xor_sync(0xffffffffu, r, o);
        if (t == 0) red[0] = r;
    }
    __syncthreads();
    float out = red[0];
    __syncthreads();
    return out;
}

__device__ __forceinline__ float block_reduce_max(float v, float* red) {
    int t = threadIdx.x, lane = t & 31, w = t >> 5;
    #pragma unroll
    for (int o = 16; o > 0; o >>= 1) v = fmaxf(v, __shfl_xor_sync(0xffffffffu, v, o));
    if (lane == 0) red[w] = v;
    __syncthreads();
    int nw = (blockDim.x + 31) >> 5;
    float r = (t < nw) ? red[t] : -3.4e38f;
    if (w == 0) {
        #pragma unroll
        for (int o = 16; o > 0; o >>= 1) r = fmaxf(r, __shfl_xor_sync(0xffffffffu, r, o));
        if (t == 0) red[0] = r;
    }
    __syncthreads();
    float out = red[0];
    __syncthreads();
    return out;
}

// ---------------- SGEMM: C[M,N] = A[M,K] @ B[K,N] (+bias, +silu, +=C) ----------------
// BM=BN=64, BK=16, 256 threads, 4x4 per thread.
template<int ACC, int ACT>
__global__ void sgemm_kernel(const float* __restrict__ A, const float* __restrict__ Bm,
                             const float* __restrict__ bias, float* __restrict__ Cm,
                             int M, int N, int K) {
    __shared__ float sA[16][64];
    __shared__ float sB[16][64];
    const int bx = blockIdx.x;     // N tile
    const int by = blockIdx.y;     // M tile
    const int tid = threadIdx.x;   // 0..255
    const int tx = tid & 15;
    const int ty = tid >> 4;
    float acc[4][4] = {};
    const float* Ab = A + (size_t)by * 64 * K;
    const float* Bb = Bm + (size_t)bx * 64;

    for (int kt = 0; kt < K; kt += 16) {
        {   // A tile 64x16 (store transposed)
            int row = tid >> 2;
            int col = (tid & 3) * 4;
            float4 a = *(const float4*)(Ab + (size_t)row * K + kt + col);
            sA[col + 0][row] = a.x; sA[col + 1][row] = a.y;
            sA[col + 2][row] = a.z; sA[col + 3][row] = a.w;
        }
        {   // B tile 16x64
            int row = tid >> 4;
            int col = (tid & 15) * 4;
            float4 b = *(const float4*)(Bb + (size_t)(kt + row) * N + col);
            *(float4*)(&sB[row][col]) = b;
        }
        __syncthreads();
        #pragma unroll
        for (int k = 0; k < 16; k++) {
            float ra[4], rb[4];
            #pragma unroll
            for (int i = 0; i < 4; i++) ra[i] = sA[k][ty * 4 + i];
            #pragma unroll
            for (int j = 0; j < 4; j++) rb[j] = sB[k][tx * 4 + j];
            #pragma unroll
            for (int i = 0; i < 4; i++)
                #pragma unroll
                for (int j = 0; j < 4; j++)
                    acc[i][j] = fmaf(ra[i], rb[j], acc[i][j]);
        }
        __syncthreads();
    }
    #pragma unroll
    for (int i = 0; i < 4; i++) {
        int r = by * 64 + ty * 4 + i;
        #pragma unroll
        for (int j = 0; j < 4; j++) {
            int c = bx * 64 + tx * 4 + j;
            float vv = acc[i][j];
            if (bias) vv += bias[c];
            if (ACT == 1) vv = vv / (1.f + expf(-vv));   // silu
            size_t idx = (size_t)r * N + c;
            if (ACC) vv += Cm[idx];
            Cm[idx] = vv;
        }
    }
}

static void launch_sgemm(const float* A, const float* B, const float* bias, float* C,
                         int M, int N, int K, int acc, int act) {
    dim3 grid(N / 64, M / 64);
    if (acc == 0 && act == 0) sgemm_kernel<0,0><<<grid,256>>>(A,B,bias,C,M,N,K);
    else if (acc == 1 && act == 0) sgemm_kernel<1,0><<<grid,256>>>(A,B,bias,C,M,N,K);
    else sgemm_kernel<0,1><<<grid,256>>>(A,B,bias,C,M,N,K);
}

// ---------------- embedding gather + pad flags ----------------
__global__ void embed_kernel(const int* __restrict__ tokens, const int* __restrict__ ctx,
                             const float* __restrict__ embed, float* __restrict__ x,
                             unsigned char* __restrict__ pad) {
    int row = blockIdx.x;                 // b*LL + l
    int b = row >> 10, l = row & 1023;
    int tok = (l < CC) ? ctx[b * CC + l] : tokens[b * SS + (l - CC)];
    if (threadIdx.x == 0) pad[row] = (tok == 0) ? 1 : 0;
    const float4* e = (const float4*)(embed + (size_t)tok * HH);
    float4* xr = (float4*)(x + (size_t)row * HH);
    xr[threadIdx.x] = e[threadIdx.x];     // 256 threads * float4 = 1024
}

// ---------------- rmsnorm ----------------
__global__ void rmsnorm_kernel(const float* __restrict__ x, const float* __restrict__ g,
                               float* __restrict__ out) {
    __shared__ float red[33];
    int row = blockIdx.x;
    int t = threadIdx.x;                  // 256
    const float4* xr = (const float4*)(x + (size_t)row * HH);
    float4 v = xr[t];
    float s = v.x*v.x + v.y*v.y + v.z*v.z + v.w*v.w;
    s = block_reduce_sum(s, red);
    float rs = rsqrtf(s / (float)HH + 1e-6f);
    float4 gg = ((const float4*)g)[t];
    float4 o; o.x = v.x*rs*gg.x; o.y = v.y*rs*gg.y; o.z = v.z*rs*gg.z; o.w = v.w*rs*gg.w;
    ((float4*)(out + (size_t)row * HH))[t] = o;
}

// ---------------- RoPE (in-place on q and k) ----------------
__global__ void rope_kernel(float* __restrict__ q, float* __restrict__ k) {
    int row = blockIdx.x;                 // b*LL + p
    int p = row & 1023;
    int t = threadIdx.x;                  // 0..1023  (16 heads * 64 dims)
    int d = t & 63;
    int i = d & 31;
    float invf = expf(-logf(10000.f) * (float)i / 32.f);
    float ang = (float)p * invf;
    float c = cosf(ang), s = sinf(ang);
    size_t idx = (size_t)row * HH + t;
    size_t idx2 = (d < 32) ? (idx + 32) : (idx - 32);
    float qd = q[idx], kd = k[idx];
    float qo = (d < 32) ? -q[idx2] : q[idx2];
    float ko = (d < 32) ? -k[idx2] : k[idx2];
    __syncthreads();
    q[idx] = qd * c + qo * s;
    k[idx] = kd * c + ko * s;
}

// ---------------- fused attention: scores+mask+softmax+PV per (b,h,q) ----------------
__global__ void attn_kernel(const float* __restrict__ q, const float* __restrict__ k,
                            const float* __restrict__ v, const float* __restrict__ ru,
                            const unsigned char* __restrict__ pad, float* __restrict__ out) {
    const int qi = blockIdx.x, h = blockIdx.y, b = blockIdx.z;
    __shared__ float sc[LL];
    __shared__ float qv[HD];
    __shared__ float red[33];
    __shared__ float pout[128];
    const int t = threadIdx.x;            // 128
    if (t < HD) qv[t] = q[(size_t)(b * LL + qi) * HH + h * HD + t];
    __syncthreads();
    const bool padq = pad[b * LL + qi] != 0;
    const float* rrow = ru + (size_t)b * LL * LL + (size_t)qi * LL;

    float lm = -3.4e38f;
    #pragma unroll
    for (int r = 0; r < LL / 128; r++) {
        int kk = r * 128 + t;
        const float4* kp = (const float4*)(k + (size_t)(b * LL + kk) * HH + h * HD);
        float d = 0.f;
        #pragma unroll
        for (int i = 0; i < HD / 4; i++) {
            float4 kv = kp[i];
            d = fmaf(kv.x, qv[4*i+0], d);
            d = fmaf(kv.y, qv[4*i+1], d);
            d = fmaf(kv.z, qv[4*i+2], d);
            d = fmaf(kv.w, qv[4*i+3], d);
        }
        bool mk = ((kk <= qi) || (rrow[kk] < 0.1f)) && !padq && (pad[b * LL + kk] == 0);
        float s = d * 0.125f + (mk ? 0.f : NEGINF);
        sc[kk] = s;
        lm = fmaxf(lm, s);
    }
    float m = block_reduce_max(lm, red);
    float ls = 0.f;
    #pragma unroll
    for (int r = 0; r < LL / 128; r++) {
        int kk = r * 128 + t;
        float e = expf(sc[kk] - m);
        sc[kk] = e;
        ls += e;
    }
    float ssum = block_reduce_sum(ls, red);
    float inv = 1.f / ssum;

    int d = t & 63, half = t >> 6;
    const float* vb = v + (size_t)(b * LL + half * 512) * HH + h * HD + d;
    float o = 0.f;
    #pragma unroll 4
    for (int kk = 0; kk < 512; kk++)
        o = fmaf(sc[half * 512 + kk], vb[(size_t)kk * HH], o);
    pout[t] = o;
    __syncthreads();
    if (t < HD)
        out[(size_t)(b * LL + qi) * HH + h * HD + t] = (pout[t] + pout[t + 64]) * inv;
}

// ---------------- silu(g)*u elementwise (silu already applied to a) ----------------
__global__ void mul_kernel(float* __restrict__ a, const float* __restrict__ b, int n4) {
    int i = blockIdx.x * blockDim.x + threadIdx.x;
    if (i < n4) {
        float4 x = ((float4*)a)[i];
        float4 y = ((const float4*)b)[i];
        x.x *= y.x; x.y *= y.y; x.z *= y.z; x.w *= y.w;
        ((float4*)a)[i] = x;
    }
}

// ---------------- build xc = concat(hs, time-embed) ----------------
__global__ void build_xc_kernel(const float* __restrict__ xn, const float* __restrict__ tvec,
                                float* __restrict__ xc) {
    int row = blockIdx.x;                 // b*SS + s
    int b = row >> 9, s = row & 511;
    const float* src = xn + (size_t)(b * LL + CC + s) * HH;
    float* dst = xc + (size_t)row * (HH + TDIM);
    float tb = tvec[b];
    for (int j = threadIdx.x; j < HH + TDIM; j += blockDim.x) {
        float val;
        if (j < HH) val = src[j];
        else {
            int jj = j - HH;
            int i = (jj < 256) ? jj : (jj - 256);
            float fr = expf(-logf(10000.f) * (float)i / 256.f);
            float a = tb * fr;
            val = (jj < 256) ? sinf(a) : cosf(a);
        }
        dst[j] = val;
    }
}

// ---------------- rate head stage 2: (B*S,512)@(512,3)+b -> softplus*mask ----------------
__global__ void rate2_kernel(const float* __restrict__ hsrc, const float* __restrict__ w2,
                             const float* __restrict__ b2, const unsigned char* __restrict__ pad,
                             float* __restrict__ out) {
    int row = blockIdx.x;                 // b*SS + s
    int b = row >> 9, s = row & 511;
    bool pd = pad[b * LL + CC + s] != 0;
    int t = threadIdx.x;                  // 128
    float a0 = 0.f, a1 = 0.f, a2 = 0.f;
    for (int kk = t; kk < TDIM; kk += 128) {
        float hv = hsrc[(size_t)row * TDIM + kk];
        const float* w = w2 + kk * 3;
        a0 = fmaf(hv, w[0], a0);
        a1 = fmaf(hv, w[1], a1);
        a2 = fmaf(hv, w[2], a2);
    }
    __shared__ float s0[128], s1[128], s2[128];
    s0[t] = a0; s1[t] = a1; s2[t] = a2;
    __syncthreads();
    for (int o = 64; o > 0; o >>= 1) {
        if (t < o) { s0[t] += s0[t+o]; s1[t] += s1[t+o]; s2[t] += s2[t+o]; }
        __syncthreads();
    }
    if (t == 0) {
        float vals[3] = { s0[0] + b2[0], s1[0] + b2[1], s2[0] + b2[2] };
        #pragma unroll
        for (int c = 0; c < 3; c++) {
            float x = vals[c];
            float sp = fmaxf(x, 0.f) + log1pf(expf(-fabsf(x)));
            out[(size_t)row * 3 + c] = pd ? 0.f : sp;
        }
    }
}

// ---------------- softmax over V=32000 (in place) * mask ----------------
__global__ void softmaxV_kernel(float* __restrict__ logits, const unsigned char* __restrict__ pad) {
    __shared__ float red[33];
    int row = blockIdx.x;                 // b*SS + s
    int b = row >> 9, s = row & 511;
    float* lr = logits + (size_t)row * VV;
    int t = threadIdx.x;                  // 256
    bool pd = pad[b * LL + CC + s] != 0;
    if (pd) {
        for (int i = t; i < VV; i += 256) lr[i] = 0.f;
        return;
    }
    float m = -3.4e38f;
    for (int i = t; i < VV; i += 256) m = fmaxf(m, lr[i]);
    m = block_reduce_max(m, red);
    float sum = 0.f;
    for (int i = t; i < VV; i += 256) {
        float e = expf(lr[i] - m);
        lr[i] = e;
        sum += e;
    }
    sum = block_reduce_sum(sum, red);
    float inv = 1.f / sum;
    for (int i = t; i < VV; i += 256) lr[i] *= inv;
}

// ---------------- launch ----------------
extern "C" void kernel_launch(void* const* d_in, const int* in_sizes, int n_in,
                              void* d_out, int out_size) {
    const int*   tokens  = (const int*)  d_in[0];
    const float* tvec    = (const float*)d_in[1];
    const int*   ctx     = (const int*)  d_in[3];
    const float* ru      = (const float*)d_in[5];
    const float* embed   = (const float*)d_in[6];
    const float* Wq      = (const float*)d_in[7];
    const float* Wk      = (const float*)d_in[8];
    const float* Wv      = (const float*)d_in[9];
    const float* Wo      = (const float*)d_in[10];
    const float* Wg      = (const float*)d_in[11];
    const float* Wu      = (const float*)d_in[12];
    const float* Wd      = (const float*)d_in[13];
    const float* ln1     = (const float*)d_in[14];
    const float* ln2     = (const float*)d_in[15];
    const float* finln   = (const float*)d_in[16];
    const float* rate_w1 = (const float*)d_in[17];
    const float* rate_b1 = (const float*)d_in[18];
    const float* rate_w2 = (const float*)d_in[19];
    const float* rate_b2 = (const float*)d_in[20];
    const float* ins_w1  = (const float*)d_in[21];
    const float* ins_b1  = (const float*)d_in[22];
    const float* ins_w2  = (const float*)d_in[23];
    const float* ins_b2  = (const float*)d_in[24];
    const float* sub_w1  = (const float*)d_in[25];
    const float* sub_b1  = (const float*)d_in[26];
    const float* sub_w2  = (const float*)d_in[27];
    const float* sub_b2  = (const float*)d_in[28];

    float *x, *xn, *q, *k, *v, *att, *m1, *m2, *xc, *h1, *hr;
    unsigned char* pad;
    cudaGetSymbolAddress((void**)&x,   g_x);
    cudaGetSymbolAddress((void**)&xn,  g_xn);
    cudaGetSymbolAddress((void**)&q,   g_q);
    cudaGetSymbolAddress((void**)&k,   g_k);
    cudaGetSymbolAddress((void**)&v,   g_v);
    cudaGetSymbolAddress((void**)&att, g_att);
    cudaGetSymbolAddress((void**)&m1,  g_m1);
    cudaGetSymbolAddress((void**)&m2,  g_m2);
    cudaGetSymbolAddress((void**)&xc,  g_xc);
    cudaGetSymbolAddress((void**)&h1,  g_h1);
    cudaGetSymbolAddress((void**)&hr,  g_hr);
    cudaGetSymbolAddress((void**)&pad, g_pad);

    float* out = (float*)d_out;
    const int M = BB * LL;                // 2048
    const size_t HHsz = (size_t)HH * HH;  // per-layer attn weight size
    const size_t HFsz = (size_t)HH * FF;

    embed_kernel<<<BB * LL, 256>>>(tokens, ctx, embed, x, pad);

    for (int l = 0; l < NLAYER; l++) {
        rmsnorm_kernel<<<M, 256>>>(x, ln1 + (size_t)l * HH, xn);
        launch_sgemm(xn, Wq + l * HHsz, nullptr, q, M, HH, HH, 0, 0);
        launch_sgemm(xn, Wk + l * HHsz, nullptr, k, M, HH, HH, 0, 0);
        launch_sgemm(xn, Wv + l * HHsz, nullptr, v, M, HH, HH, 0, 0);
        rope_kernel<<<M, 1024>>>(q, k);
        attn_kernel<<<dim3(LL, NHEAD, BB), 128>>>(q, k, v, ru, pad, att);
        launch_sgemm(att, Wo + l * HHsz, nullptr, x, M, HH, HH, 1, 0);   // x += att@Wo
        rmsnorm_kernel<<<M, 256>>>(x, ln2 + (size_t)l * HH, xn);
        launch_sgemm(xn, Wg + l * HFsz, nullptr, m1, M, FF, HH, 0, 1);   // silu
        launch_sgemm(xn, Wu + l * HFsz, nullptr, m2, M, FF, HH, 0, 0);
        mul_kernel<<<(M * FF / 4 + 255) / 256, 256>>>(m1, m2, M * FF / 4);
        launch_sgemm(m1, Wd + (size_t)l * FF * HH, nullptr, x, M, HH, FF, 1, 0); // x += h@Wd
    }

    rmsnorm_kernel<<<M, 256>>>(x, finln, xn);
    build_xc_kernel<<<BB * SS, 256>>>(xn, tvec, xc);

    const int BS = BB * SS;               // 1024
    // rate head
    launch_sgemm(xc, rate_w1, rate_b1, hr, BS, TDIM, HH + TDIM, 0, 1);
    rate2_kernel<<<BS, 128>>>(hr, rate_w2, rate_b2, pad, out);

    const size_t INS_OFF = (size_t)BS * 3;
    const size_t SUB_OFF = INS_OFF + (size_t)BS * VV;

    // ins head
    launch_sgemm(xc, ins_w1, ins_b1, h1, BS, HH, HH + TDIM, 0, 1);
    launch_sgemm(h1, ins_w2, ins_b2, out + INS_OFF, BS, VV, HH, 0, 0);
    softmaxV_kernel<<<BS, 256>>>(out + INS_OFF, pad);

    // sub head
    launch_sgemm(xc, sub_w1, sub_b1, h1, BS, HH, HH + TDIM, 0, 1);
    launch_sgemm(h1, sub_w2, sub_b2, out + SUB_OFF, BS, VV, HH, 0, 0);
    softmaxV_kernel<<<BS, 256>>>(out + SUB_OFF, pad);
}

// round 3
// speedup vs baseline: 1.4630x; 1.4630x over previous
#include <cuda_runtime.h>
#include <cuda_bf16.h>
#include <math.h>
#include <stdint.h>

// ---------------- problem constants ----------------
#define BB 2
#define SS 512
#define CC 512
#define LL 1024
#define HH 1024
#define NHEAD 16
#define HD 64
#define FF 4096
#define NLAYER 4
#define VV 32000
#define TDIM 512
#define NEGINF (-1000000000.0f)

// ---------------- scratch (device globals; no allocs allowed) ----------------
__device__ float g_x  [BB*LL*HH];
__device__ float g_xn [BB*LL*HH];
__device__ float g_q  [BB*LL*HH];
__device__ float g_k  [BB*LL*HH];
__device__ float g_v  [BB*LL*HH];
__device__ float g_att[BB*LL*HH];
__device__ float g_m1 [BB*LL*FF];
__device__ float g_m2 [BB*LL*FF];
__device__ float g_xc [BB*SS*(HH+TDIM)];
__device__ float g_h1 [BB*SS*HH];
__device__ float g_hr [BB*SS*TDIM];
__device__ unsigned char g_pad[BB*LL];

// ---------------- block reductions ----------------
__device__ __forceinline__ float block_reduce_sum(float v, float* red) {
    int t = threadIdx.x, lane = t & 31, w = t >> 5;
    #pragma unroll
    for (int o = 16; o > 0; o >>= 1) v += __shfl_xor_sync(0xffffffffu, v, o);
    if (lane == 0) red[w] = v;
    __syncthreads();
    int nw = (blockDim.x + 31) >> 5;
    float r = (t < nw) ? red[t] : 0.f;
    if (w == 0) {
        #pragma unroll
        for (int o = 16; o > 0; o >>= 1) r += __shfl_xor_sync(0xffffffffu, r, o);
        if (t == 0) red[0] = r;
    }
    __syncthreads();
    float out = red[0];
    __syncthreads();
    return out;
}

__device__ __forceinline__ float block_reduce_max(float v, float* red) {
    int t = threadIdx.x, lane = t & 31, w = t >> 5;
    #pragma unroll
    for (int o = 16; o > 0; o >>= 1) v = fmaxf(v, __shfl_xor_sync(0xffffffffu, v, o));
    if (lane == 0) red[w] = v;
    __syncthreads();
    int nw = (blockDim.x + 31) >> 5;
    float r = (t < nw) ? red[t] : -3.4e38f;
    if (w == 0) {
        #pragma unroll
        for (int o = 16; o > 0; o >>= 1) r = fmaxf(r, __shfl_xor_sync(0xffffffffu, r, o));
        if (t == 0) red[0] = r;
    }
    __syncthreads();
    float out = red[0];
    __syncthreads();
    return out;
}

// ---------------- TF32 tensor-core GEMM ----------------
// C[M,N] = A[M,K] @ B[K,N]  (+bias, optional silu, optional +=C)
// Block tile 128x128, BK=32. 256 threads = 8 warps (2 m x 4 n), warp tile 64x32.
// mma.sync.aligned.m16n8k8.row.col.f32.tf32.tf32.f32
// Requires: M%128==0, N%128==0, K%32==0. All satisfied here.

__device__ __forceinline__ uint32_t f2tf32(float f) {
    uint32_t r;
    asm volatile("cvt.rna.tf32.f32 %0, %1;" : "=r"(r) : "f"(f));
    return r;
}

#define SA_STRIDE 36
#define SB_STRIDE 136

template<int ACC, int ACT>
__global__ __launch_bounds__(256)
void gemm_tf32_kernel(const float* __restrict__ A, const float* __restrict__ Bm,
                      const float* __restrict__ bias, float* __restrict__ Cm,
                      int M, int N, int K) {
    __shared__ uint32_t sA[128 * SA_STRIDE];   // [row][k]
    __shared__ uint32_t sB[32  * SB_STRIDE];   // [k][col]

    const int tid = threadIdx.x;
    const int lane = tid & 31;
    const int warp = tid >> 5;
    const int warp_m = warp >> 2;     // 0..1 -> m offset *64
    const int warp_n = warp & 3;      // 0..3 -> n offset *32
    const int g  = lane >> 2;         // group 0..7
    const int t4 = lane & 3;          // 0..3

    const int bm = blockIdx.y;
    const int bn = blockIdx.x;

    float acc[4][4][4];               // [mt][nt][frag]
    #pragma unroll
    for (int i = 0; i < 4; i++)
        #pragma unroll
        for (int j = 0; j < 4; j++)
            #pragma unroll
            for (int f = 0; f < 4; f++) acc[i][j][f] = 0.f;

    // fill-thread mapping
    const int a_row  = tid >> 1;            // 0..127
    const int a_col0 = (tid & 1) * 16;      // 0 or 16
    const int b_row  = tid >> 3;            // 0..31
    const int b_col0 = (tid & 7) * 16;      // 0..112

    const float* Ab = A + (size_t)(bm * 128 + a_row) * K + a_col0;
    const float* Bb = Bm + (size_t)b_row * N + bn * 128 + b_col0;

    for (int kt = 0; kt < K; kt += 32) {
        // ---- fill A tile 128x32 ----
        {
            const float* src = Ab + kt;
            uint32_t* dst = &sA[a_row * SA_STRIDE + a_col0];
            #pragma unroll
            for (int j = 0; j < 4; j++) {
                float4 vv = *(const float4*)(src + j * 4);
                dst[j*4+0] = f2tf32(vv.x); dst[j*4+1] = f2tf32(vv.y);
                dst[j*4+2] = f2tf32(vv.z); dst[j*4+3] = f2tf32(vv.w);
            }
        }
        // ---- fill B tile 32x128 ----
        {
            const float* src = Bb + (size_t)kt * N;
            uint32_t* dst = &sB[b_row * SB_STRIDE + b_col0];
            #pragma unroll
            for (int j = 0; j < 4; j++) {
                float4 vv = *(const float4*)(src + j * 4);
                dst[j*4+0] = f2tf32(vv.x); dst[j*4+1] = f2tf32(vv.y);
                dst[j*4+2] = f2tf32(vv.z); dst[j*4+3] = f2tf32(vv.w);
            }
        }
        __syncthreads();

        #pragma unroll
        for (int ks = 0; ks < 4; ks++) {
            const int k0 = ks * 8;
            uint32_t af[4][4];    // [mt][frag]
            uint32_t bf[4][2];    // [nt][frag]
            #pragma unroll
            for (int mt = 0; mt < 4; mt++) {
                int rb = warp_m * 64 + mt * 16;
                af[mt][0] = sA[(rb + g    ) * SA_STRIDE + k0 + t4    ];
                af[mt][1] = sA[(rb + g + 8) * SA_STRIDE + k0 + t4    ];
                af[mt][2] = sA[(rb + g    ) * SA_STRIDE + k0 + t4 + 4];
                af[mt][3] = sA[(rb + g + 8) * SA_STRIDE + k0 + t4 + 4];
            }
            #pragma unroll
            for (int nt = 0; nt < 4; nt++) {
                int cb = warp_n * 32 + nt * 8 + g;
                bf[nt][0] = sB[(k0 + t4    ) * SB_STRIDE + cb];
                bf[nt][1] = sB[(k0 + t4 + 4) * SB_STRIDE + cb];
            }
            #pragma unroll
            for (int mt = 0; mt < 4; mt++)
                #pragma unroll
                for (int nt = 0; nt < 4; nt++) {
                    asm volatile(
                        "mma.sync.aligned.m16n8k8.row.col.f32.tf32.tf32.f32 "
                        "{%0,%1,%2,%3}, {%4,%5,%6,%7}, {%8,%9}, {%0,%1,%2,%3};"
                        : "+f"(acc[mt][nt][0]), "+f"(acc[mt][nt][1]),
                          "+f"(acc[mt][nt][2]), "+f"(acc[mt][nt][3])
                        : "r"(af[mt][0]), "r"(af[mt][1]), "r"(af[mt][2]), "r"(af[mt][3]),
                          "r"(bf[nt][0]), "r"(bf[nt][1]));
                }
        }
        __syncthreads();
    }

    // ---- epilogue ----
    #pragma unroll
    for (int mt = 0; mt < 4; mt++) {
        int row0 = bm * 128 + warp_m * 64 + mt * 16 + g;
        #pragma unroll
        for (int nt = 0; nt < 4; nt++) {
            int col0 = bn * 128 + warp_n * 32 + nt * 8 + t4 * 2;
            #pragma unroll
            for (int f = 0; f < 4; f++) {
                int r = row0 + ((f & 2) ? 8 : 0);
                int c = col0 + (f & 1);
                float vv = acc[mt][nt][f];
                if (bias) vv += bias[c];
                if (ACT == 1) vv = vv / (1.f + expf(-vv));   // silu
                size_t idx = (size_t)r * N + c;
                if (ACC) vv += Cm[idx];
                Cm[idx] = vv;
            }
        }
    }
}

static void launch_gemm(const float* A, const float* B, const float* bias, float* C,
                        int M, int N, int K, int acc, int act) {
    dim3 grid(N / 128, M / 128);
    if (acc == 0 && act == 0) gemm_tf32_kernel<0,0><<<grid,256>>>(A,B,bias,C,M,N,K);
    else if (acc == 1 && act == 0) gemm_tf32_kernel<1,0><<<grid,256>>>(A,B,bias,C,M,N,K);
    else gemm_tf32_kernel<0,1><<<grid,256>>>(A,B,bias,C,M,N,K);
}

// ---------------- embedding gather + pad flags ----------------
__global__ void embed_kernel(const int* __restrict__ tokens, const int* __restrict__ ctx,
                             const float* __restrict__ embed, float* __restrict__ x,
                             unsigned char* __restrict__ pad) {
    int row = blockIdx.x;                 // b*LL + l
    int b = row >> 10, l = row & 1023;
    int tok = (l < CC) ? ctx[b * CC + l] : tokens[b * SS + (l - CC)];
    if (threadIdx.x == 0) pad[row] = (tok == 0) ? 1 : 0;
    const float4* e = (const float4*)(embed + (size_t)tok * HH);
    float4* xr = (float4*)(x + (size_t)row * HH);
    xr[threadIdx.x] = e[threadIdx.x];     // 256 threads * float4 = 1024
}

// ---------------- rmsnorm ----------------
__global__ void rmsnorm_kernel(const float* __restrict__ x, const float* __restrict__ g,
                               float* __restrict__ out) {
    __shared__ float red[33];
    int row = blockIdx.x;
    int t = threadIdx.x;                  // 256
    const float4* xr = (const float4*)(x + (size_t)row * HH);
    float4 v = xr[t];
    float s = v.x*v.x + v.y*v.y + v.z*v.z + v.w*v.w;
    s = block_reduce_sum(s, red);
    float rs = rsqrtf(s / (float)HH + 1e-6f);
    float4 gg = ((const float4*)g)[t];
    float4 o; o.x = v.x*rs*gg.x; o.y = v.y*rs*gg.y; o.z = v.z*rs*gg.z; o.w = v.w*rs*gg.w;
    ((float4*)(out + (size_t)row * HH))[t] = o;
}

// ---------------- RoPE (in-place on q and k) ----------------
__global__ void rope_kernel(float* __restrict__ q, float* __restrict__ k) {
    int row = blockIdx.x;                 // b*LL + p
    int p = row & 1023;
    int t = threadIdx.x;                  // 0..1023  (16 heads * 64 dims)
    int d = t & 63;
    int i = d & 31;
    float invf = expf(-logf(10000.f) * (float)i / 32.f);
    float ang = (float)p * invf;
    float c = cosf(ang), s = sinf(ang);
    size_t idx = (size_t)row * HH + t;
    size_t idx2 = (d < 32) ? (idx + 32) : (idx - 32);
    float qd = q[idx], kd = k[idx];
    float qo = (d < 32) ? -q[idx2] : q[idx2];
    float ko = (d < 32) ? -k[idx2] : k[idx2];
    __syncthreads();
    q[idx] = qd * c + qo * s;
    k[idx] = kd * c + ko * s;
}

// ---------------- fused attention: scores+mask+softmax+PV per (b,h,q) ----------------
__global__ void attn_kernel(const float* __restrict__ q, const float* __restrict__ k,
                            const float* __restrict__ v, const float* __restrict__ ru,
                            const unsigned char* __restrict__ pad, float* __restrict__ out) {
    const int qi = blockIdx.x, h = blockIdx.y, b = blockIdx.z;
    __shared__ float sc[LL];
    __shared__ float qv[HD];
    __shared__ float red[33];
    __shared__ float pout[128];
    const int t = threadIdx.x;            // 128
    if (t < HD) qv[t] = q[(size_t)(b * LL + qi) * HH + h * HD + t];
    __syncthreads();
    const bool padq = pad[b * LL + qi] != 0;
    const float* rrow = ru + (size_t)b * LL * LL + (size_t)qi * LL;

    float lm = -3.4e38f;
    #pragma unroll
    for (int r = 0; r < LL / 128; r++) {
        int kk = r * 128 + t;
        const float4* kp = (const float4*)(k + (size_t)(b * LL + kk) * HH + h * HD);
        float d = 0.f;
        #pragma unroll
        for (int i = 0; i < HD / 4; i++) {
            float4 kv = kp[i];
            d = fmaf(kv.x, qv[4*i+0], d);
            d = fmaf(kv.y, qv[4*i+1], d);
            d = fmaf(kv.z, qv[4*i+2], d);
            d = fmaf(kv.w, qv[4*i+3], d);
        }
        bool mk = ((kk <= qi) || (rrow[kk] < 0.1f)) && !padq && (pad[b * LL + kk] == 0);
        float s = d * 0.125f + (mk ? 0.f : NEGINF);
        sc[kk] = s;
        lm = fmaxf(lm, s);
    }
    float m = block_reduce_max(lm, red);
    float ls = 0.f;
    #pragma unroll
    for (int r = 0; r < LL / 128; r++) {
        int kk = r * 128 + t;
        float e = expf(sc[kk] - m);
        sc[kk] = e;
        ls += e;
    }
    float ssum = block_reduce_sum(ls, red);
    float inv = 1.f / ssum;

    int d = t & 63, half = t >> 6;
    const float* vb = v + (size_t)(b * LL + half * 512) * HH + h * HD + d;
    float o = 0.f;
    #pragma unroll 4
    for (int kk = 0; kk < 512; kk++)
        o = fmaf(sc[half * 512 + kk], vb[(size_t)kk * HH], o);
    pout[t] = o;
    __syncthreads();
    if (t < HD)
        out[(size_t)(b * LL + qi) * HH + h * HD + t] = (pout[t] + pout[t + 64]) * inv;
}

// ---------------- silu(g)*u elementwise (silu already applied to a) ----------------
__global__ void mul_kernel(float* __restrict__ a, const float* __restrict__ b, int n4) {
    int i = blockIdx.x * blockDim.x + threadIdx.x;
    if (i < n4) {
        float4 x = ((float4*)a)[i];
        float4 y = ((const float4*)b)[i];
        x.x *= y.x; x.y *= y.y; x.z *= y.z; x.w *= y.w;
        ((float4*)a)[i] = x;
    }
}

// ---------------- build xc = concat(hs, time-embed) ----------------
__global__ void build_xc_kernel(const float* __restrict__ xn, const float* __restrict__ tvec,
                                float* __restrict__ xc) {
    int row = blockIdx.x;                 // b*SS + s
    int b = row >> 9, s = row & 511;
    const float* src = xn + (size_t)(b * LL + CC + s) * HH;
    float* dst = xc + (size_t)row * (HH + TDIM);
    float tb = tvec[b];
    for (int j = threadIdx.x; j < HH + TDIM; j += blockDim.x) {
        float val;
        if (j < HH) val = src[j];
        else {
            int jj = j - HH;
            int i = (jj < 256) ? jj : (jj - 256);
            float fr = expf(-logf(10000.f) * (float)i / 256.f);
            float a = tb * fr;
            val = (jj < 256) ? sinf(a) : cosf(a);
        }
        dst[j] = val;
    }
}

// ---------------- rate head stage 2: (B*S,512)@(512,3)+b -> softplus*mask ----------------
__global__ void rate2_kernel(const float* __restrict__ hsrc, const float* __restrict__ w2,
                             const float* __restrict__ b2, const unsigned char* __restrict__ pad,
                             float* __restrict__ out) {
    int row = blockIdx.x;                 // b*SS + s
    int b = row >> 9, s = row & 511;
    bool pd = pad[b * LL + CC + s] != 0;
    int t = threadIdx.x;                  // 128
    float a0 = 0.f, a1 = 0.f, a2 = 0.f;
    for (int kk = t; kk < TDIM; kk += 128) {
        float hv = hsrc[(size_t)row * TDIM + kk];
        const float* w = w2 + kk * 3;
        a0 = fmaf(hv, w[0], a0);
        a1 = fmaf(hv, w[1], a1);
        a2 = fmaf(hv, w[2], a2);
    }
    __shared__ float s0[128], s1[128], s2[128];
    s0[t] = a0; s1[t] = a1; s2[t] = a2;
    __syncthreads();
    for (int o = 64; o > 0; o >>= 1) {
        if (t < o) { s0[t] += s0[t+o]; s1[t] += s1[t+o]; s2[t] += s2[t+o]; }
        __syncthreads();
    }
    if (t == 0) {
        float vals[3] = { s0[0] + b2[0], s1[0] + b2[1], s2[0] + b2[2] };
        #pragma unroll
        for (int c = 0; c < 3; c++) {
            float x = vals[c];
            float sp = fmaxf(x, 0.f) + log1pf(expf(-fabsf(x)));
            out[(size_t)row * 3 + c] = pd ? 0.f : sp;
        }
    }
}

// ---------------- softmax over V=32000 (in place) * mask ----------------
__global__ void softmaxV_kernel(float* __restrict__ logits, const unsigned char* __restrict__ pad) {
    __shared__ float red[33];
    int row = blockIdx.x;                 // b*SS + s
    int b = row >> 9, s = row & 511;
    float* lr = logits + (size_t)row * VV;
    int t = threadIdx.x;                  // 256
    bool pd = pad[b * LL + CC + s] != 0;
    if (pd) {
        for (int i = t; i < VV; i += 256) lr[i] = 0.f;
        return;
    }
    float m = -3.4e38f;
    for (int i = t; i < VV; i += 256) m = fmaxf(m, lr[i]);
    m = block_reduce_max(m, red);
    float sum = 0.f;
    for (int i = t; i < VV; i += 256) {
        float e = expf(lr[i] - m);
        lr[i] = e;
        sum += e;
    }
    sum = block_reduce_sum(sum, red);
    float inv = 1.f / sum;
    for (int i = t; i < VV; i += 256) lr[i] *= inv;
}

// ---------------- launch ----------------
extern "C" void kernel_launch(void* const* d_in, const int* in_sizes, int n_in,
                              void* d_out, int out_size) {
    const int*   tokens  = (const int*)  d_in[0];
    const float* tvec    = (const float*)d_in[1];
    const int*   ctx     = (const int*)  d_in[3];
    const float* ru      = (const float*)d_in[5];
    const float* embed   = (const float*)d_in[6];
    const float* Wq      = (const float*)d_in[7];
    const float* Wk      = (const float*)d_in[8];
    const float* Wv      = (const float*)d_in[9];
    const float* Wo      = (const float*)d_in[10];
    const float* Wg      = (const float*)d_in[11];
    const float* Wu      = (const float*)d_in[12];
    const float* Wd      = (const float*)d_in[13];
    const float* ln1     = (const float*)d_in[14];
    const float* ln2     = (const float*)d_in[15];
    const float* finln   = (const float*)d_in[16];
    const float* rate_w1 = (const float*)d_in[17];
    const float* rate_b1 = (const float*)d_in[18];
    const float* rate_w2 = (const float*)d_in[19];
    const float* rate_b2 = (const float*)d_in[20];
    const float* ins_w1  = (const float*)d_in[21];
    const float* ins_b1  = (const float*)d_in[22];
    const float* ins_w2  = (const float*)d_in[23];
    const float* ins_b2  = (const float*)d_in[24];
    const float* sub_w1  = (const float*)d_in[25];
    const float* sub_b1  = (const float*)d_in[26];
    const float* sub_w2  = (const float*)d_in[27];
    const float* sub_b2  = (const float*)d_in[28];

    float *x, *xn, *q, *k, *v, *att, *m1, *m2, *xc, *h1, *hr;
    unsigned char* pad;
    cudaGetSymbolAddress((void**)&x,   g_x);
    cudaGetSymbolAddress((void**)&xn,  g_xn);
    cudaGetSymbolAddress((void**)&q,   g_q);
    cudaGetSymbolAddress((void**)&k,   g_k);
    cudaGetSymbolAddress((void**)&v,   g_v);
    cudaGetSymbolAddress((void**)&att, g_att);
    cudaGetSymbolAddress((void**)&m1,  g_m1);
    cudaGetSymbolAddress((void**)&m2,  g_m2);
    cudaGetSymbolAddress((void**)&xc,  g_xc);
    cudaGetSymbolAddress((void**)&h1,  g_h1);
    cudaGetSymbolAddress((void**)&hr,  g_hr);
    cudaGetSymbolAddress((void**)&pad, g_pad);

    float* out = (float*)d_out;
    const int M = BB * LL;                // 2048
    const size_t HHsz = (size_t)HH * HH;  // per-layer attn weight size
    const size_t HFsz = (size_t)HH * FF;

    embed_kernel<<<BB * LL, 256>>>(tokens, ctx, embed, x, pad);

    for (int l = 0; l < NLAYER; l++) {
        rmsnorm_kernel<<<M, 256>>>(x, ln1 + (size_t)l * HH, xn);
        launch_gemm(xn, Wq + l * HHsz, nullptr, q, M, HH, HH, 0, 0);
        launch_gemm(xn, Wk + l * HHsz, nullptr, k, M, HH, HH, 0, 0);
        launch_gemm(xn, Wv + l * HHsz, nullptr, v, M, HH, HH, 0, 0);
        rope_kernel<<<M, 1024>>>(q, k);
        attn_kernel<<<dim3(LL, NHEAD, BB), 128>>>(q, k, v, ru, pad, att);
        launch_gemm(att, Wo + l * HHsz, nullptr, x, M, HH, HH, 1, 0);    // x += att@Wo
        rmsnorm_kernel<<<M, 256>>>(x, ln2 + (size_t)l * HH, xn);
        launch_gemm(xn, Wg + l * HFsz, nullptr, m1, M, FF, HH, 0, 1);    // silu
        launch_gemm(xn, Wu + l * HFsz, nullptr, m2, M, FF, HH, 0, 0);
        mul_kernel<<<(M * FF / 4 + 255) / 256, 256>>>(m1, m2, M * FF / 4);
        launch_gemm(m1, Wd + (size_t)l * FF * HH, nullptr, x, M, HH, FF, 1, 0); // x += h@Wd
    }

    rmsnorm_kernel<<<M, 256>>>(x, finln, xn);
    build_xc_kernel<<<BB * SS, 256>>>(xn, tvec, xc);

    const int BS = BB * SS;               // 1024
    // rate head
    launch_gemm(xc, rate_w1, rate_b1, hr, BS, TDIM, HH + TDIM, 0, 1);
    rate2_kernel<<<BS, 128>>>(hr, rate_w2, rate_b2, pad, out);

    const size_t INS_OFF = (size_t)BS * 3;
    const size_t SUB_OFF = INS_OFF + (size_t)BS * VV;

    // ins head
    launch_gemm(xc, ins_w1, ins_b1, h1, BS, HH, HH + TDIM, 0, 1);
    launch_gemm(h1, ins_w2, ins_b2, out + INS_OFF, BS, VV, HH, 0, 0);
    softmaxV_kernel<<<BS, 256>>>(out + INS_OFF, pad);

    // sub head
    launch_gemm(xc, sub_w1, sub_b1, h1, BS, HH, HH + TDIM, 0, 1);
    launch_gemm(h1, sub_w2, sub_b2, out + SUB_OFF, BS, VV, HH, 0, 0);
    softmaxV_kernel<<<BS, 256>>>(out + SUB_OFF, pad);
}

// round 4
// speedup vs baseline: 3.5038x; 2.3949x over previous
#include <cuda_runtime.h>
#include <cuda_bf16.h>
#include <math.h>
#include <stdint.h>

// ---------------- problem constants ----------------
#define BB 2
#define SS 512
#define CC 512
#define LL 1024
#define HH 1024
#define NHEAD 16
#define HD 64
#define FF 4096
#define NLAYER 4
#define VV 32000
#define TDIM 512
#define NEGINF (-1000000000.0f)

// ---------------- scratch (device globals; no allocs allowed) ----------------
__device__ float g_x  [BB*LL*HH];
__device__ float g_xn [BB*LL*HH];
__device__ float g_q  [BB*LL*HH];
__device__ float g_k  [BB*LL*HH];
__device__ float g_v  [BB*LL*HH];
__device__ float g_att[BB*LL*HH];
__device__ float g_m1 [BB*LL*FF];
__device__ float g_m2 [BB*LL*FF];
__device__ float g_xc [BB*SS*(HH+TDIM)];
__device__ float g_h1 [BB*SS*HH];
__device__ float g_hr [BB*SS*TDIM];
__device__ unsigned char g_pad[BB*LL];

// ---------------- block reductions ----------------
__device__ __forceinline__ float block_reduce_sum(float v, float* red) {
    int t = threadIdx.x, lane = t & 31, w = t >> 5;
    #pragma unroll
    for (int o = 16; o > 0; o >>= 1) v += __shfl_xor_sync(0xffffffffu, v, o);
    if (lane == 0) red[w] = v;
    __syncthreads();
    int nw = (blockDim.x + 31) >> 5;
    float r = (t < nw) ? red[t] : 0.f;
    if (w == 0) {
        #pragma unroll
        for (int o = 16; o > 0; o >>= 1) r += __shfl_xor_sync(0xffffffffu, r, o);
        if (t == 0) red[0] = r;
    }
    __syncthreads();
    float out = red[0];
    __syncthreads();
    return out;
}

__device__ __forceinline__ float block_reduce_max(float v, float* red) {
    int t = threadIdx.x, lane = t & 31, w = t >> 5;
    #pragma unroll
    for (int o = 16; o > 0; o >>= 1) v = fmaxf(v, __shfl_xor_sync(0xffffffffu, v, o));
    if (lane == 0) red[w] = v;
    __syncthreads();
    int nw = (blockDim.x + 31) >> 5;
    float r = (t < nw) ? red[t] : -3.4e38f;
    if (w == 0) {
        #pragma unroll
        for (int o = 16; o > 0; o >>= 1) r = fmaxf(r, __shfl_xor_sync(0xffffffffu, r, o));
        if (t == 0) red[0] = r;
    }
    __syncthreads();
    float out = red[0];
    __syncthreads();
    return out;
}

// ---------------- helpers ----------------
__device__ __forceinline__ uint32_t f2tf32(float f) {
    uint32_t r;
    asm volatile("cvt.rna.tf32.f32 %0, %1;" : "=r"(r) : "f"(f));
    return r;
}

__device__ __forceinline__ void cp_async16(void* dst, const void* src) {
    uint32_t d = (uint32_t)__cvta_generic_to_shared(dst);
    asm volatile("cp.async.cg.shared.global [%0], [%1], 16;\n" :: "r"(d), "l"(src));
}
#define CP_ASYNC_COMMIT() asm volatile("cp.async.commit_group;\n" ::)
#define CP_ASYNC_WAIT(N)  asm volatile("cp.async.wait_group %0;\n" :: "n"(N))

// ---------------- TF32 tensor-core GEMM, cp.async double-buffered ----------------
// C[M,N] = A[M,K] @ B[K,N] (+bias, optional silu, optional +=C)
// Block tile 128x128, BK=32. 256 threads = 8 warps (2m x 4n), warp tile 64x32.
#define GA_STRIDE 36
#define GB_STRIDE 136
#define A_STAGE (128*GA_STRIDE)
#define B_STAGE (32*GB_STRIDE)
#define GEMM_SMEM_BYTES ((2*(A_STAGE + B_STAGE)) * 4)

template<int ACC, int ACT>
__device__ __forceinline__ void gemm_core(const float* __restrict__ A, const float* __restrict__ Bm,
                                          const float* __restrict__ bias, float* __restrict__ Cm,
                                          int M, int N, int K, float* sm) {
    float* sA0 = sm;
    float* sB0 = sm + 2 * A_STAGE;
    const int tid = threadIdx.x;
    const int lane = tid & 31;
    const int warp = tid >> 5;
    const int warp_m = warp >> 2;
    const int warp_n = warp & 3;
    const int g  = lane >> 2;
    const int t4 = lane & 3;
    const int bm = blockIdx.y;
    const int bn = blockIdx.x;

    float acc[4][4][4] = {};

    const int a_row  = tid >> 1;
    const int a_col0 = (tid & 1) * 16;
    const int b_row  = tid >> 3;
    const int b_col0 = (tid & 7) * 16;
    const float* Agp = A  + (size_t)(bm * 128 + a_row) * K + a_col0;
    const float* Bgp = Bm + (size_t)b_row * N + (size_t)bn * 128 + b_col0;

    const int KT = K >> 5;

    // prologue: stage 0
    {
        float* da = sA0 + a_row * GA_STRIDE + a_col0;
        float* db = sB0 + b_row * GB_STRIDE + b_col0;
        #pragma unroll
        for (int j = 0; j < 4; j++) cp_async16(da + j*4, Agp + j*4);
        #pragma unroll
        for (int j = 0; j < 4; j++) cp_async16(db + j*4, Bgp + j*4);
        CP_ASYNC_COMMIT();
    }

    for (int kt = 0; kt < KT; kt++) {
        if (kt + 1 < KT) {
            int st = (kt + 1) & 1;
            float* da = sA0 + st * A_STAGE + a_row * GA_STRIDE + a_col0;
            float* db = sB0 + st * B_STAGE + b_row * GB_STRIDE + b_col0;
            const float* sa = Agp + (kt + 1) * 32;
            const float* sb = Bgp + (size_t)(kt + 1) * 32 * N;
            #pragma unroll
            for (int j = 0; j < 4; j++) cp_async16(da + j*4, sa + j*4);
            #pragma unroll
            for (int j = 0; j < 4; j++) cp_async16(db + j*4, sb + j*4);
            CP_ASYNC_COMMIT();
            CP_ASYNC_WAIT(1);
        } else {
            CP_ASYNC_WAIT(0);
        }
        __syncthreads();
        const float* sa = sA0 + (kt & 1) * A_STAGE;
        const float* sb = sB0 + (kt & 1) * B_STAGE;
        #pragma unroll
        for (int ks = 0; ks < 4; ks++) {
            const int k0 = ks * 8;
            uint32_t af[4][4];
            uint32_t bf[4][2];
            #pragma unroll
            for (int mt = 0; mt < 4; mt++) {
                int rb_ = warp_m * 64 + mt * 16;
                af[mt][0] = f2tf32(sa[(rb_ + g    ) * GA_STRIDE + k0 + t4    ]);
                af[mt][1] = f2tf32(sa[(rb_ + g + 8) * GA_STRIDE + k0 + t4    ]);
                af[mt][2] = f2tf32(sa[(rb_ + g    ) * GA_STRIDE + k0 + t4 + 4]);
                af[mt][3] = f2tf32(sa[(rb_ + g + 8) * GA_STRIDE + k0 + t4 + 4]);
            }
            #pragma unroll
            for (int nt = 0; nt < 4; nt++) {
                int cb = warp_n * 32 + nt * 8 + g;
                bf[nt][0] = f2tf32(sb[(k0 + t4    ) * GB_STRIDE + cb]);
                bf[nt][1] = f2tf32(sb[(k0 + t4 + 4) * GB_STRIDE + cb]);
            }
            #pragma unroll
            for (int mt = 0; mt < 4; mt++)
                #pragma unroll
                for (int nt = 0; nt < 4; nt++) {
                    asm volatile(
                        "mma.sync.aligned.m16n8k8.row.col.f32.tf32.tf32.f32 "
                        "{%0,%1,%2,%3}, {%4,%5,%6,%7}, {%8,%9}, {%0,%1,%2,%3};"
                        : "+f"(acc[mt][nt][0]), "+f"(acc[mt][nt][1]),
                          "+f"(acc[mt][nt][2]), "+f"(acc[mt][nt][3])
                        : "r"(af[mt][0]), "r"(af[mt][1]), "r"(af[mt][2]), "r"(af[mt][3]),
                          "r"(bf[nt][0]), "r"(bf[nt][1]));
                }
        }
        __syncthreads();
    }

    #pragma unroll
    for (int mt = 0; mt < 4; mt++) {
        int row0 = bm * 128 + warp_m * 64 + mt * 16 + g;
        #pragma unroll
        for (int nt = 0; nt < 4; nt++) {
            int col0 = bn * 128 + warp_n * 32 + nt * 8 + t4 * 2;
            #pragma unroll
            for (int f = 0; f < 4; f++) {
                int r = row0 + ((f & 2) ? 8 : 0);
                int c = col0 + (f & 1);
                float vv = acc[mt][nt][f];
                if (bias) vv += bias[c];
                if (ACT == 1) vv = vv / (1.f + expf(-vv));
                size_t idx = (size_t)r * N + c;
                if (ACC) vv += Cm[idx];
                Cm[idx] = vv;
            }
        }
    }
}

template<int ACC, int ACT>
__global__ __launch_bounds__(256, 2)
void gemm_async_kernel(const float* __restrict__ A, const float* __restrict__ Bm,
                       const float* __restrict__ bias, float* __restrict__ Cm,
                       int M, int N, int K) {
    extern __shared__ float sm[];
    gemm_core<ACC, ACT>(A, Bm, bias, Cm, M, N, K, sm);
}

struct QKVPtrs { const float *Bq, *Bk, *Bv; float *Cq, *Ck, *Cv; };

__global__ __launch_bounds__(256, 2)
void gemm_qkv_kernel(const float* __restrict__ A, QKVPtrs p, int M, int N, int K) {
    extern __shared__ float sm[];
    const float* Bm = (blockIdx.z == 0) ? p.Bq : (blockIdx.z == 1) ? p.Bk : p.Bv;
    float*       Cm = (blockIdx.z == 0) ? p.Cq : (blockIdx.z == 1) ? p.Ck : p.Cv;
    gemm_core<0, 0>(A, Bm, nullptr, Cm, M, N, K, sm);
}

// ---------------- embedding gather + pad flags ----------------
__global__ void embed_kernel(const int* __restrict__ tokens, const int* __restrict__ ctx,
                             const float* __restrict__ embed, float* __restrict__ x,
                             unsigned char* __restrict__ pad) {
    int row = blockIdx.x;
    int b = row >> 10, l = row & 1023;
    int tok = (l < CC) ? ctx[b * CC + l] : tokens[b * SS + (l - CC)];
    if (threadIdx.x == 0) pad[row] = (tok == 0) ? 1 : 0;
    const float4* e = (const float4*)(embed + (size_t)tok * HH);
    float4* xr = (float4*)(x + (size_t)row * HH);
    xr[threadIdx.x] = e[threadIdx.x];
}

// ---------------- rmsnorm ----------------
__global__ void rmsnorm_kernel(const float* __restrict__ x, const float* __restrict__ g,
                               float* __restrict__ out) {
    __shared__ float red[33];
    int row = blockIdx.x;
    int t = threadIdx.x;
    const float4* xr = (const float4*)(x + (size_t)row * HH);
    float4 v = xr[t];
    float s = v.x*v.x + v.y*v.y + v.z*v.z + v.w*v.w;
    s = block_reduce_sum(s, red);
    float rs = rsqrtf(s / (float)HH + 1e-6f);
    float4 gg = ((const float4*)g)[t];
    float4 o; o.x = v.x*rs*gg.x; o.y = v.y*rs*gg.y; o.z = v.z*rs*gg.z; o.w = v.w*rs*gg.w;
    ((float4*)(out + (size_t)row * HH))[t] = o;
}

// ---------------- RoPE (in-place on q and k) ----------------
__global__ void rope_kernel(float* __restrict__ q, float* __restrict__ k) {
    int row = blockIdx.x;
    int p = row & 1023;
    int t = threadIdx.x;
    int d = t & 63;
    int i = d & 31;
    float invf = expf(-logf(10000.f) * (float)i / 32.f);
    float ang = (float)p * invf;
    float c = cosf(ang), s = sinf(ang);
    size_t idx = (size_t)row * HH + t;
    size_t idx2 = (d < 32) ? (idx + 32) : (idx - 32);
    float qd = q[idx], kd = k[idx];
    float qo = (d < 32) ? -q[idx2] : q[idx2];
    float ko = (d < 32) ? -k[idx2] : k[idx2];
    __syncthreads();
    q[idx] = qd * c + qo * s;
    k[idx] = kd * c + ko * s;
}

// ---------------- flash-style attention: 64 q-rows per block ----------------
// grid (LL/64, NHEAD, BB), 256 threads (16x16), online softmax, fp32.
#define AT_STRIDE 68
#define ATTN_SMEM_BYTES (4 * 64 * AT_STRIDE * 4)

__global__ __launch_bounds__(256, 2)
void attn_flash_kernel(const float* __restrict__ q, const float* __restrict__ k,
                       const float* __restrict__ v, const float* __restrict__ ru,
                       const unsigned char* __restrict__ pad, float* __restrict__ out) {
    extern __shared__ float sm[];
    float* sQ  = sm;                       // [64][AT_STRIDE] rows
    float* sKT = sQ  + 64 * AT_STRIDE;     // [d][r]
    float* sV  = sKT + 64 * AT_STRIDE;     // [r][d]
    float* sP  = sV  + 64 * AT_STRIDE;     // [r][j]

    const int qt = blockIdx.x, h = blockIdx.y, b = blockIdx.z;
    const int t = threadIdx.x;
    const int tx = t & 15, ty = t >> 4;
    const int q0 = qt * 64;

    // load Q tile
    {
        int r = t >> 2;
        int d0 = (t & 3) * 16;
        const float* src = q + (size_t)(b * LL + q0 + r) * HH + h * HD + d0;
        float* dst = sQ + r * AT_STRIDE + d0;
        #pragma unroll
        for (int j = 0; j < 4; j++) *(float4*)(dst + j*4) = *(const float4*)(src + j*4);
    }

    float m_i[4], l_i[4], O[4][4];
    unsigned char pq[4];
    #pragma unroll
    for (int i = 0; i < 4; i++) {
        m_i[i] = -3.4e38f; l_i[i] = 0.f;
        pq[i] = pad[b * LL + q0 + ty * 4 + i];
        #pragma unroll
        for (int j = 0; j < 4; j++) O[i][j] = 0.f;
    }

    for (int c = 0; c < LL / 64; c++) {
        const int kbase = c * 64;
        __syncthreads();                   // all readers of prev chunk done
        // load K transposed + V rows
        {
            int r = t >> 2;
            int d0 = (t & 3) * 16;
            const float* ks = k + (size_t)(b * LL + kbase + r) * HH + h * HD + d0;
            const float* vs = v + (size_t)(b * LL + kbase + r) * HH + h * HD + d0;
            #pragma unroll
            for (int j = 0; j < 4; j++) {
                float4 kv = *(const float4*)(ks + j*4);
                sKT[(d0 + j*4 + 0) * AT_STRIDE + r] = kv.x;
                sKT[(d0 + j*4 + 1) * AT_STRIDE + r] = kv.y;
                sKT[(d0 + j*4 + 2) * AT_STRIDE + r] = kv.z;
                sKT[(d0 + j*4 + 3) * AT_STRIDE + r] = kv.w;
                *(float4*)(sV + r * AT_STRIDE + d0 + j*4) = *(const float4*)(vs + j*4);
            }
        }
        __syncthreads();

        // S = Q K^T  (4x4 per thread)
        float S[4][4] = {};
        #pragma unroll
        for (int d = 0; d < HD; d += 4) {
            float4 ra[4], rb[4];
            #pragma unroll
            for (int i = 0; i < 4; i++) ra[i] = *(const float4*)(sQ + (ty*4 + i) * AT_STRIDE + d);
            #pragma unroll
            for (int e = 0; e < 4; e++) rb[e] = *(const float4*)(sKT + (d + e) * AT_STRIDE + tx*4);
            #pragma unroll
            for (int i = 0; i < 4; i++) {
                float ax = ra[i].x, ay = ra[i].y, az = ra[i].z, aw = ra[i].w;
                S[i][0] = fmaf(ax, rb[0].x, fmaf(ay, rb[1].x, fmaf(az, rb[2].x, fmaf(aw, rb[3].x, S[i][0]))));
                S[i][1] = fmaf(ax, rb[0].y, fmaf(ay, rb[1].y, fmaf(az, rb[2].y, fmaf(aw, rb[3].y, S[i][1]))));
                S[i][2] = fmaf(ax, rb[0].z, fmaf(ay, rb[1].z, fmaf(az, rb[2].z, fmaf(aw, rb[3].z, S[i][2]))));
                S[i][3] = fmaf(ax, rb[0].w, fmaf(ay, rb[1].w, fmaf(az, rb[2].w, fmaf(aw, rb[3].w, S[i][3]))));
            }
        }

        // mask
        unsigned char pk[4];
        #pragma unroll
        for (int j = 0; j < 4; j++) pk[j] = pad[b * LL + kbase + tx*4 + j];
        #pragma unroll
        for (int i = 0; i < 4; i++) {
            int qg = q0 + ty*4 + i;
            const float* rr = ru + ((size_t)b * LL + qg) * LL + kbase + tx*4;
            float4 r4 = *(const float4*)rr;
            bool okq = (pq[i] == 0);
            float rv[4] = { r4.x, r4.y, r4.z, r4.w };
            #pragma unroll
            for (int j = 0; j < 4; j++) {
                int kg = kbase + tx*4 + j;
                bool ok = ((kg <= qg) || (rv[j] < 0.1f)) && okq && (pk[j] == 0);
                S[i][j] = S[i][j] * 0.125f + (ok ? 0.f : NEGINF);
            }
        }

        // online softmax update + write P
        #pragma unroll
        for (int i = 0; i < 4; i++) {
            float mx = fmaxf(fmaxf(S[i][0], S[i][1]), fmaxf(S[i][2], S[i][3]));
            #pragma unroll
            for (int o = 1; o < 16; o <<= 1) mx = fmaxf(mx, __shfl_xor_sync(0xffffffffu, mx, o));
            float mn = fmaxf(m_i[i], mx);
            float sc = expf(m_i[i] - mn);
            float p0 = expf(S[i][0] - mn), p1 = expf(S[i][1] - mn);
            float p2 = expf(S[i][2] - mn), p3 = expf(S[i][3] - mn);
            float rs = p0 + p1 + p2 + p3;
            #pragma unroll
            for (int o = 1; o < 16; o <<= 1) rs += __shfl_xor_sync(0xffffffffu, rs, o);
            l_i[i] = l_i[i] * sc + rs;
            m_i[i] = mn;
            #pragma unroll
            for (int j = 0; j < 4; j++) O[i][j] *= sc;
            float* pp = sP + (ty*4 + i) * AT_STRIDE + tx*4;
            pp[0] = p0; pp[1] = p1; pp[2] = p2; pp[3] = p3;
        }
        __syncwarp();

        // O += P @ V
        #pragma unroll
        for (int j = 0; j < 64; j += 4) {
            float4 pa[4], vb[4];
            #pragma unroll
            for (int i = 0; i < 4; i++) pa[i] = *(const float4*)(sP + (ty*4 + i) * AT_STRIDE + j);
            #pragma unroll
            for (int e = 0; e < 4; e++) vb[e] = *(const float4*)(sV + (j + e) * AT_STRIDE + tx*4);
            #pragma unroll
            for (int i = 0; i < 4; i++) {
                float ax = pa[i].x, ay = pa[i].y, az = pa[i].z, aw = pa[i].w;
                O[i][0] = fmaf(ax, vb[0].x, fmaf(ay, vb[1].x, fmaf(az, vb[2].x, fmaf(aw, vb[3].x, O[i][0]))));
                O[i][1] = fmaf(ax, vb[0].y, fmaf(ay, vb[1].y, fmaf(az, vb[2].y, fmaf(aw, vb[3].y, O[i][1]))));
                O[i][2] = fmaf(ax, vb[0].z, fmaf(ay, vb[1].z, fmaf(az, vb[2].z, fmaf(aw, vb[3].z, O[i][2]))));
                O[i][3] = fmaf(ax, vb[0].w, fmaf(ay, vb[1].w, fmaf(az, vb[2].w, fmaf(aw, vb[3].w, O[i][3]))));
            }
        }
    }

    #pragma unroll
    for (int i = 0; i < 4; i++) {
        float inv = 1.f / l_i[i];
        float4 o4;
        o4.x = O[i][0] * inv; o4.y = O[i][1] * inv; o4.z = O[i][2] * inv; o4.w = O[i][3] * inv;
        *(float4*)(out + (size_t)(b * LL + q0 + ty*4 + i) * HH + h * HD + tx*4) = o4;
    }
}

// ---------------- silu(g)*u elementwise (silu already applied to a) ----------------
__global__ void mul_kernel(float* __restrict__ a, const float* __restrict__ b, int n4) {
    int i = blockIdx.x * blockDim.x + threadIdx.x;
    if (i < n4) {
        float4 x = ((float4*)a)[i];
        float4 y = ((const float4*)b)[i];
        x.x *= y.x; x.y *= y.y; x.z *= y.z; x.w *= y.w;
        ((float4*)a)[i] = x;
    }
}

// ---------------- build xc = concat(hs, time-embed) ----------------
__global__ void build_xc_kernel(const float* __restrict__ xn, const float* __restrict__ tvec,
                                float* __restrict__ xc) {
    int row = blockIdx.x;
    int b = row >> 9, s = row & 511;
    const float* src = xn + (size_t)(b * LL + CC + s) * HH;
    float* dst = xc + (size_t)row * (HH + TDIM);
    float tb = tvec[b];
    for (int j = threadIdx.x; j < HH + TDIM; j += blockDim.x) {
        float val;
        if (j < HH) val = src[j];
        else {
            int jj = j - HH;
            int i = (jj < 256) ? jj : (jj - 256);
            float fr = expf(-logf(10000.f) * (float)i / 256.f);
            float a = tb * fr;
            val = (jj < 256) ? sinf(a) : cosf(a);
        }
        dst[j] = val;
    }
}

// ---------------- rate head stage 2 ----------------
__global__ void rate2_kernel(const float* __restrict__ hsrc, const float* __restrict__ w2,
                             const float* __restrict__ b2, const unsigned char* __restrict__ pad,
                             float* __restrict__ out) {
    int row = blockIdx.x;
    int b = row >> 9, s = row & 511;
    bool pd = pad[b * LL + CC + s] != 0;
    int t = threadIdx.x;
    float a0 = 0.f, a1 = 0.f, a2 = 0.f;
    for (int kk = t; kk < TDIM; kk += 128) {
        float hv = hsrc[(size_t)row * TDIM + kk];
        const float* w = w2 + kk * 3;
        a0 = fmaf(hv, w[0], a0);
        a1 = fmaf(hv, w[1], a1);
        a2 = fmaf(hv, w[2], a2);
    }
    __shared__ float s0[128], s1[128], s2[128];
    s0[t] = a0; s1[t] = a1; s2[t] = a2;
    __syncthreads();
    for (int o = 64; o > 0; o >>= 1) {
        if (t < o) { s0[t] += s0[t+o]; s1[t] += s1[t+o]; s2[t] += s2[t+o]; }
        __syncthreads();
    }
    if (t == 0) {
        float vals[3] = { s0[0] + b2[0], s1[0] + b2[1], s2[0] + b2[2] };
        #pragma unroll
        for (int c = 0; c < 3; c++) {
            float x = vals[c];
            float sp = fmaxf(x, 0.f) + log1pf(expf(-fabsf(x)));
            out[(size_t)row * 3 + c] = pd ? 0.f : sp;
        }
    }
}

// ---------------- softmax over V=32000 (in place) * mask ----------------
__global__ void softmaxV_kernel(float* __restrict__ logits, const unsigned char* __restrict__ pad) {
    __shared__ float red[33];
    int row = blockIdx.x;
    int b = row >> 9, s = row & 511;
    float* lr = logits + (size_t)row * VV;
    int t = threadIdx.x;
    bool pd = pad[b * LL + CC + s] != 0;
    if (pd) {
        for (int i = t; i < VV; i += 256) lr[i] = 0.f;
        return;
    }
    float m = -3.4e38f;
    for (int i = t; i < VV; i += 256) m = fmaxf(m, lr[i]);
    m = block_reduce_max(m, red);
    float sum = 0.f;
    for (int i = t; i < VV; i += 256) {
        float e = expf(lr[i] - m);
        lr[i] = e;
        sum += e;
    }
    sum = block_reduce_sum(sum, red);
    float inv = 1.f / sum;
    for (int i = t; i < VV; i += 256) lr[i] *= inv;
}

// ---------------- host helpers ----------------
static void launch_gemm(const float* A, const float* B, const float* bias, float* C,
                        int M, int N, int K, int acc, int act) {
    dim3 grid(N / 128, M / 128);
    if (acc == 0 && act == 0) gemm_async_kernel<0,0><<<grid,256,GEMM_SMEM_BYTES>>>(A,B,bias,C,M,N,K);
    else if (acc == 1 && act == 0) gemm_async_kernel<1,0><<<grid,256,GEMM_SMEM_BYTES>>>(A,B,bias,C,M,N,K);
    else gemm_async_kernel<0,1><<<grid,256,GEMM_SMEM_BYTES>>>(A,B,bias,C,M,N,K);
}

// ---------------- launch ----------------
extern "C" void kernel_launch(void* const* d_in, const int* in_sizes, int n_in,
                              void* d_out, int out_size) {
    const int*   tokens  = (const int*)  d_in[0];
    const float* tvec    = (const float*)d_in[1];
    const int*   ctx     = (const int*)  d_in[3];
    const float* ru      = (const float*)d_in[5];
    const float* embed   = (const float*)d_in[6];
    const float* Wq      = (const float*)d_in[7];
    const float* Wk      = (const float*)d_in[8];
    const float* Wv      = (const float*)d_in[9];
    const float* Wo      = (const float*)d_in[10];
    const float* Wg      = (const float*)d_in[11];
    const float* Wu      = (const float*)d_in[12];
    const float* Wd      = (const float*)d_in[13];
    const float* ln1     = (const float*)d_in[14];
    const float* ln2     = (const float*)d_in[15];
    const float* finln   = (const float*)d_in[16];
    const float* rate_w1 = (const float*)d_in[17];
    const float* rate_b1 = (const float*)d_in[18];
    const float* rate_w2 = (const float*)d_in[19];
    const float* rate_b2 = (const float*)d_in[20];
    const float* ins_w1  = (const float*)d_in[21];
    const float* ins_b1  = (const float*)d_in[22];
    const float* ins_w2  = (const float*)d_in[23];
    const float* ins_b2  = (const float*)d_in[24];
    const float* sub_w1  = (const float*)d_in[25];
    const float* sub_b1  = (const float*)d_in[26];
    const float* sub_w2  = (const float*)d_in[27];
    const float* sub_b2  = (const float*)d_in[28];

    // one-time smem opt-ins (idempotent)
    cudaFuncSetAttribute(gemm_async_kernel<0,0>, cudaFuncAttributeMaxDynamicSharedMemorySize, GEMM_SMEM_BYTES);
    cudaFuncSetAttribute(gemm_async_kernel<1,0>, cudaFuncAttributeMaxDynamicSharedMemorySize, GEMM_SMEM_BYTES);
    cudaFuncSetAttribute(gemm_async_kernel<0,1>, cudaFuncAttributeMaxDynamicSharedMemorySize, GEMM_SMEM_BYTES);
    cudaFuncSetAttribute(gemm_qkv_kernel,        cudaFuncAttributeMaxDynamicSharedMemorySize, GEMM_SMEM_BYTES);
    cudaFuncSetAttribute(attn_flash_kernel,      cudaFuncAttributeMaxDynamicSharedMemorySize, ATTN_SMEM_BYTES);

    float *x, *xn, *q, *k, *v, *att, *m1, *m2, *xc, *h1, *hr;
    unsigned char* pad;
    cudaGetSymbolAddress((void**)&x,   g_x);
    cudaGetSymbolAddress((void**)&xn,  g_xn);
    cudaGetSymbolAddress((void**)&q,   g_q);
    cudaGetSymbolAddress((void**)&k,   g_k);
    cudaGetSymbolAddress((void**)&v,   g_v);
    cudaGetSymbolAddress((void**)&att, g_att);
    cudaGetSymbolAddress((void**)&m1,  g_m1);
    cudaGetSymbolAddress((void**)&m2,  g_m2);
    cudaGetSymbolAddress((void**)&xc,  g_xc);
    cudaGetSymbolAddress((void**)&h1,  g_h1);
    cudaGetSymbolAddress((void**)&hr,  g_hr);
    cudaGetSymbolAddress((void**)&pad, g_pad);

    float* out = (float*)d_out;
    const int M = BB * LL;
    const size_t HHsz = (size_t)HH * HH;
    const size_t HFsz = (size_t)HH * FF;

    embed_kernel<<<BB * LL, 256>>>(tokens, ctx, embed, x, pad);

    for (int l = 0; l < NLAYER; l++) {
        rmsnorm_kernel<<<M, 256>>>(x, ln1 + (size_t)l * HH, xn);
        QKVPtrs p { Wq + l * HHsz, Wk + l * HHsz, Wv + l * HHsz, q, k, v };
        gemm_qkv_kernel<<<dim3(HH/128, M/128, 3), 256, GEMM_SMEM_BYTES>>>(xn, p, M, HH, HH);
        rope_kernel<<<M, 1024>>>(q, k);
        attn_flash_kernel<<<dim3(LL/64, NHEAD, BB), 256, ATTN_SMEM_BYTES>>>(q, k, v, ru, pad, att);
        launch_gemm(att, Wo + l * HHsz, nullptr, x, M, HH, HH, 1, 0);
        rmsnorm_kernel<<<M, 256>>>(x, ln2 + (size_t)l * HH, xn);
        launch_gemm(xn, Wg + l * HFsz, nullptr, m1, M, FF, HH, 0, 1);
        launch_gemm(xn, Wu + l * HFsz, nullptr, m2, M, FF, HH, 0, 0);
        mul_kernel<<<(M * FF / 4 + 255) / 256, 256>>>(m1, m2, M * FF / 4);
        launch_gemm(m1, Wd + (size_t)l * FF * HH, nullptr, x, M, HH, FF, 1, 0);
    }

    rmsnorm_kernel<<<M, 256>>>(x, finln, xn);
    build_xc_kernel<<<BB * SS, 256>>>(xn, tvec, xc);

    const int BS = BB * SS;
    launch_gemm(xc, rate_w1, rate_b1, hr, BS, TDIM, HH + TDIM, 0, 1);
    rate2_kernel<<<BS, 128>>>(hr, rate_w2, rate_b2, pad, out);

    const size_t INS_OFF = (size_t)BS * 3;
    const size_t SUB_OFF = INS_OFF + (size_t)BS * VV;

    launch_gemm(xc, ins_w1, ins_b1, h1, BS, HH, HH + TDIM, 0, 1);
    launch_gemm(h1, ins_w2, ins_b2, out + INS_OFF, BS, VV, HH, 0, 0);
    softmaxV_kernel<<<BS, 256>>>(out + INS_OFF, pad);

    launch_gemm(xc, sub_w1, sub_b1, h1, BS, HH, HH + TDIM, 0, 1);
    launch_gemm(h1, sub_w2, sub_b2, out + SUB_OFF, BS, VV, HH, 0, 0);
    softmaxV_kernel<<<BS, 256>>>(out + SUB_OFF, pad);
}

// round 5
// speedup vs baseline: 5.8331x; 1.6648x over previous
#include <cuda_runtime.h>
#include <cuda_fp16.h>
#include <math.h>
#include <stdint.h>

// ---------------- problem constants ----------------
#define BB 2
#define SS 512
#define CC 512
#define LL 1024
#define HH 1024
#define NHEAD 16
#define HD 64
#define FF 4096
#define NLAYER 4
#define VV 32000
#define TDIM 512
#define NEGINF (-1000000000.0f)

// ---------------- scratch (device globals; no allocs allowed) ----------------
__device__ float g_x  [BB*LL*HH];
__device__ float g_q  [BB*LL*HH];
__device__ float g_k  [BB*LL*HH];
__device__ float g_v  [BB*LL*HH];
__device__ float g_m1 [BB*LL*FF];
__device__ float g_m2 [BB*LL*FF];
__device__ float g_hr [BB*SS*TDIM];
__device__ unsigned char g_pad[BB*LL];

// half activations
__device__ __half g_xnh [BB*LL*HH];
__device__ __half g_atth[BB*LL*HH];
__device__ __half g_m1h [BB*LL*FF];
__device__ __half g_xch [BB*SS*(HH+TDIM)];
__device__ __half g_h1h [BB*SS*HH];

// half weight pool (filled once per launch)
#define WH_TOTAL 136577024
__device__ __half g_wh[WH_TOTAL];

// ---------------- block reductions ----------------
__device__ __forceinline__ float block_reduce_sum(float v, float* red) {
    int t = threadIdx.x, lane = t & 31, w = t >> 5;
    #pragma unroll
    for (int o = 16; o > 0; o >>= 1) v += __shfl_xor_sync(0xffffffffu, v, o);
    if (lane == 0) red[w] = v;
    __syncthreads();
    int nw = (blockDim.x + 31) >> 5;
    float r = (t < nw) ? red[t] : 0.f;
    if (w == 0) {
        #pragma unroll
        for (int o = 16; o > 0; o >>= 1) r += __shfl_xor_sync(0xffffffffu, r, o);
        if (t == 0) red[0] = r;
    }
    __syncthreads();
    float out = red[0];
    __syncthreads();
    return out;
}

__device__ __forceinline__ float block_reduce_max(float v, float* red) {
    int t = threadIdx.x, lane = t & 31, w = t >> 5;
    #pragma unroll
    for (int o = 16; o > 0; o >>= 1) v = fmaxf(v, __shfl_xor_sync(0xffffffffu, v, o));
    if (lane == 0) red[w] = v;
    __syncthreads();
    int nw = (blockDim.x + 31) >> 5;
    float r = (t < nw) ? red[t] : -3.4e38f;
    if (w == 0) {
        #pragma unroll
        for (int o = 16; o > 0; o >>= 1) r = fmaxf(r, __shfl_xor_sync(0xffffffffu, r, o));
        if (t == 0) red[0] = r;
    }
    __syncthreads();
    float out = red[0];
    __syncthreads();
    return out;
}

// ---------------- async copy helpers ----------------
__device__ __forceinline__ void cp_async16(void* dst, const void* src) {
    uint32_t d = (uint32_t)__cvta_generic_to_shared(dst);
    asm volatile("cp.async.cg.shared.global [%0], [%1], 16;\n" :: "r"(d), "l"(src));
}
#define CP_ASYNC_COMMIT() asm volatile("cp.async.commit_group;\n" ::)
#define CP_ASYNC_WAIT(N)  asm volatile("cp.async.wait_group %0;\n" :: "n"(N))

__device__ __forceinline__ void ldsm_x4(uint32_t& r0, uint32_t& r1, uint32_t& r2, uint32_t& r3, uint32_t addr) {
    asm volatile("ldmatrix.sync.aligned.m8n8.x4.shared.b16 {%0,%1,%2,%3}, [%4];"
        : "=r"(r0), "=r"(r1), "=r"(r2), "=r"(r3) : "r"(addr));
}
__device__ __forceinline__ void ldsm_x2t(uint32_t& r0, uint32_t& r1, uint32_t addr) {
    asm volatile("ldmatrix.sync.aligned.m8n8.x2.trans.shared.b16 {%0,%1}, [%2];"
        : "=r"(r0), "=r"(r1) : "r"(addr));
}

// ---------------- fp16 tensor-core GEMM, cp.async double-buffered ----------------
// C[M,N] = A[M,K] @ B[K,N] (+bias, optional silu, optional +=C fp32, optional half out)
// Block tile 128x128, BK=32. 256 threads = 8 warps (2m x 4n), warp tile 64x32.
#define HA_STRIDE 40
#define HB_STRIDE 136
#define HA_STAGE (128*HA_STRIDE)                       // halfs
#define HB_STAGE (32*HB_STRIDE)
#define HGEMM_SMEM_BYTES ((2*(HA_STAGE + HB_STAGE)) * 2)

template<int ACC, int ACT, int OUTH>
__device__ __forceinline__ void hgemm_core(const __half* __restrict__ A, const __half* __restrict__ Bm,
                                           const float* __restrict__ bias,
                                           float* __restrict__ Cf, __half* __restrict__ Ch,
                                           int M, int N, int K, __half* sm) {
    __half* sA = sm;
    __half* sB = sm + 2 * HA_STAGE;
    const int tid = threadIdx.x;
    const int lane = tid & 31;
    const int warp = tid >> 5;
    const int warp_m = warp >> 2;
    const int warp_n = warp & 3;
    const int g  = lane >> 2;
    const int t4 = lane & 3;
    const int bm = blockIdx.y;
    const int bn = blockIdx.x;

    float acc[4][4][4] = {};

    // cp.async mapping
    const int a_row = tid >> 1;             // 0..127
    const int a_col = (tid & 1) * 16;       // halfs (+8 for 2nd chunk)
    const int b_row = tid >> 3;             // 0..31
    const int b_col = (tid & 7) * 16;       // halfs (+8 for 2nd chunk)
    const __half* Agp = A  + (size_t)(bm * 128 + a_row) * K + a_col;
    const __half* Bgp = Bm + (size_t)b_row * N + (size_t)bn * 128 + b_col;

    const int KT = K >> 5;

    // ldmatrix base addresses (bytes, shared space)
    uint32_t sA_b = (uint32_t)__cvta_generic_to_shared(sA);
    uint32_t sB_b = (uint32_t)__cvta_generic_to_shared(sB);
    uint32_t aBase = sA_b + (uint32_t)(((warp_m * 64 + (lane & 15)) * HA_STRIDE + (lane >> 4) * 8) * 2);
    uint32_t bBase = sB_b + (uint32_t)((((lane & 15)) * HB_STRIDE + warp_n * 32) * 2);

    // prologue stage 0
    {
        __half* da = sA + a_row * HA_STRIDE + a_col;
        __half* db = sB + b_row * HB_STRIDE + b_col;
        cp_async16(da,     Agp);
        cp_async16(da + 8, Agp + 8);
        cp_async16(db,     Bgp);
        cp_async16(db + 8, Bgp + 8);
        CP_ASYNC_COMMIT();
    }

    for (int kt = 0; kt < KT; kt++) {
        if (kt + 1 < KT) {
            int st = (kt + 1) & 1;
            __half* da = sA + st * HA_STAGE + a_row * HA_STRIDE + a_col;
            __half* db = sB + st * HB_STAGE + b_row * HB_STRIDE + b_col;
            const __half* ga = Agp + (kt + 1) * 32;
            const __half* gb = Bgp + (size_t)(kt + 1) * 32 * N;
            cp_async16(da,     ga);
            cp_async16(da + 8, ga + 8);
            cp_async16(db,     gb);
            cp_async16(db + 8, gb + 8);
            CP_ASYNC_COMMIT();
            CP_ASYNC_WAIT(1);
        } else {
            CP_ASYNC_WAIT(0);
        }
        __syncthreads();

        uint32_t aSt = aBase + (uint32_t)((kt & 1) * HA_STAGE * 2);
        uint32_t bSt = bBase + (uint32_t)((kt & 1) * HB_STAGE * 2);

        #pragma unroll
        for (int ks = 0; ks < 2; ks++) {
            uint32_t af[4][4], bf[4][2];
            #pragma unroll
            for (int mt = 0; mt < 4; mt++)
                ldsm_x4(af[mt][0], af[mt][1], af[mt][2], af[mt][3],
                        aSt + (uint32_t)(mt * 16 * HA_STRIDE * 2 + ks * 32));
            #pragma unroll
            for (int nt = 0; nt < 4; nt++)
                ldsm_x2t(bf[nt][0], bf[nt][1],
                         bSt + (uint32_t)(ks * 16 * HB_STRIDE * 2 + nt * 16));
            #pragma unroll
            for (int mt = 0; mt < 4; mt++)
                #pragma unroll
                for (int nt = 0; nt < 4; nt++) {
                    asm volatile(
                        "mma.sync.aligned.m16n8k16.row.col.f32.f16.f16.f32 "
                        "{%0,%1,%2,%3}, {%4,%5,%6,%7}, {%8,%9}, {%0,%1,%2,%3};"
                        : "+f"(acc[mt][nt][0]), "+f"(acc[mt][nt][1]),
                          "+f"(acc[mt][nt][2]), "+f"(acc[mt][nt][3])
                        : "r"(af[mt][0]), "r"(af[mt][1]), "r"(af[mt][2]), "r"(af[mt][3]),
                          "r"(bf[nt][0]), "r"(bf[nt][1]));
                }
        }
        __syncthreads();
    }

    // epilogue
    #pragma unroll
    for (int mt = 0; mt < 4; mt++) {
        int row0 = bm * 128 + warp_m * 64 + mt * 16 + g;
        #pragma unroll
        for (int nt = 0; nt < 4; nt++) {
            int col0 = bn * 128 + warp_n * 32 + nt * 8 + t4 * 2;
            #pragma unroll
            for (int f = 0; f < 4; f++) {
                int r = row0 + ((f & 2) ? 8 : 0);
                int c = col0 + (f & 1);
                float vv = acc[mt][nt][f];
                if (bias) vv += bias[c];
                if (ACT == 1) vv = vv / (1.f + expf(-vv));
                size_t idx = (size_t)r * N + c;
                if (OUTH) {
                    Ch[idx] = __float2half_rn(vv);
                } else {
                    if (ACC) vv += Cf[idx];
                    Cf[idx] = vv;
                }
            }
        }
    }
}

template<int ACC, int ACT, int OUTH>
__global__ __launch_bounds__(256, 2)
void hgemm_kernel(const __half* __restrict__ A, const __half* __restrict__ Bm,
                  const float* __restrict__ bias, float* __restrict__ Cf, __half* __restrict__ Ch,
                  int M, int N, int K) {
    extern __shared__ __half smh[];
    hgemm_core<ACC, ACT, OUTH>(A, Bm, bias, Cf, Ch, M, N, K, smh);
}

struct QKVPtrs { const __half *Bq, *Bk, *Bv; float *Cq, *Ck, *Cv; };

__global__ __launch_bounds__(256, 2)
void hgemm_qkv_kernel(const __half* __restrict__ A, QKVPtrs p, int M, int N, int K) {
    extern __shared__ __half smh[];
    const __half* Bm = (blockIdx.z == 0) ? p.Bq : (blockIdx.z == 1) ? p.Bk : p.Bv;
    float*        Cm = (blockIdx.z == 0) ? p.Cq : (blockIdx.z == 1) ? p.Ck : p.Cv;
    hgemm_core<0, 0, 0>(A, Bm, nullptr, Cm, nullptr, M, N, K, smh);
}

// ---------------- fp32 -> fp16 conversion ----------------
__global__ void f2h_kernel(const float* __restrict__ src, __half* __restrict__ dst, int n4) {
    int i = blockIdx.x * blockDim.x + threadIdx.x;
    if (i < n4) {
        float4 v = ((const float4*)src)[i];
        __half2 h0 = __floats2half2_rn(v.x, v.y);
        __half2 h1 = __floats2half2_rn(v.z, v.w);
        ((__half2*)dst)[i * 2]     = h0;
        ((__half2*)dst)[i * 2 + 1] = h1;
    }
}

// ---------------- embedding gather + pad flags ----------------
__global__ void embed_kernel(const int* __restrict__ tokens, const int* __restrict__ ctx,
                             const float* __restrict__ embed, float* __restrict__ x,
                             unsigned char* __restrict__ pad) {
    int row = blockIdx.x;
    int b = row >> 10, l = row & 1023;
    int tok = (l < CC) ? ctx[b * CC + l] : tokens[b * SS + (l - CC)];
    if (threadIdx.x == 0) pad[row] = (tok == 0) ? 1 : 0;
    const float4* e = (const float4*)(embed + (size_t)tok * HH);
    float4* xr = (float4*)(x + (size_t)row * HH);
    xr[threadIdx.x] = e[threadIdx.x];
}

// ---------------- rmsnorm (fp32 in, fp16 out) ----------------
__global__ void rmsnorm_h_kernel(const float* __restrict__ x, const float* __restrict__ g,
                                 __half* __restrict__ out) {
    __shared__ float red[33];
    int row = blockIdx.x;
    int t = threadIdx.x;
    const float4* xr = (const float4*)(x + (size_t)row * HH);
    float4 v = xr[t];
    float s = v.x*v.x + v.y*v.y + v.z*v.z + v.w*v.w;
    s = block_reduce_sum(s, red);
    float rs = rsqrtf(s / (float)HH + 1e-6f);
    float4 gg = ((const float4*)g)[t];
    __half2 h0 = __floats2half2_rn(v.x * rs * gg.x, v.y * rs * gg.y);
    __half2 h1 = __floats2half2_rn(v.z * rs * gg.z, v.w * rs * gg.w);
    __half2* o = (__half2*)(out + (size_t)row * HH);
    o[t * 2]     = h0;
    o[t * 2 + 1] = h1;
}

// ---------------- RoPE (in-place on q and k) ----------------
__global__ void rope_kernel(float* __restrict__ q, float* __restrict__ k) {
    int row = blockIdx.x;
    int p = row & 1023;
    int t = threadIdx.x;
    int d = t & 63;
    int i = d & 31;
    float invf = expf(-logf(10000.f) * (float)i / 32.f);
    float ang = (float)p * invf;
    float c = cosf(ang), s = sinf(ang);
    size_t idx = (size_t)row * HH + t;
    size_t idx2 = (d < 32) ? (idx + 32) : (idx - 32);
    float qd = q[idx], kd = k[idx];
    float qo = (d < 32) ? -q[idx2] : q[idx2];
    float ko = (d < 32) ? -k[idx2] : k[idx2];
    __syncthreads();
    q[idx] = qd * c + qo * s;
    k[idx] = kd * c + ko * s;
}

// ---------------- flash-style attention: 64 q-rows per block, fp16 out ----------------
#define AT_STRIDE 68
#define ATTN_SMEM_BYTES (4 * 64 * AT_STRIDE * 4)

__global__ __launch_bounds__(256, 2)
void attn_flash_kernel(const float* __restrict__ q, const float* __restrict__ k,
                       const float* __restrict__ v, const float* __restrict__ ru,
                       const unsigned char* __restrict__ pad, __half* __restrict__ out) {
    extern __shared__ float sm[];
    float* sQ  = sm;
    float* sKT = sQ  + 64 * AT_STRIDE;
    float* sV  = sKT + 64 * AT_STRIDE;
    float* sP  = sV  + 64 * AT_STRIDE;

    const int qt = blockIdx.x, h = blockIdx.y, b = blockIdx.z;
    const int t = threadIdx.x;
    const int tx = t & 15, ty = t >> 4;
    const int q0 = qt * 64;

    {
        int r = t >> 2;
        int d0 = (t & 3) * 16;
        const float* src = q + (size_t)(b * LL + q0 + r) * HH + h * HD + d0;
        float* dst = sQ + r * AT_STRIDE + d0;
        #pragma unroll
        for (int j = 0; j < 4; j++) *(float4*)(dst + j*4) = *(const float4*)(src + j*4);
    }

    float m_i[4], l_i[4], O[4][4];
    unsigned char pq[4];
    #pragma unroll
    for (int i = 0; i < 4; i++) {
        m_i[i] = -3.4e38f; l_i[i] = 0.f;
        pq[i] = pad[b * LL + q0 + ty * 4 + i];
        #pragma unroll
        for (int j = 0; j < 4; j++) O[i][j] = 0.f;
    }

    for (int c = 0; c < LL / 64; c++) {
        const int kbase = c * 64;
        __syncthreads();
        {
            int r = t >> 2;
            int d0 = (t & 3) * 16;
            const float* ks = k + (size_t)(b * LL + kbase + r) * HH + h * HD + d0;
            const float* vs = v + (size_t)(b * LL + kbase + r) * HH + h * HD + d0;
            #pragma unroll
            for (int j = 0; j < 4; j++) {
                float4 kv = *(const float4*)(ks + j*4);
                sKT[(d0 + j*4 + 0) * AT_STRIDE + r] = kv.x;
                sKT[(d0 + j*4 + 1) * AT_STRIDE + r] = kv.y;
                sKT[(d0 + j*4 + 2) * AT_STRIDE + r] = kv.z;
                sKT[(d0 + j*4 + 3) * AT_STRIDE + r] = kv.w;
                *(float4*)(sV + r * AT_STRIDE + d0 + j*4) = *(const float4*)(vs + j*4);
            }
        }
        __syncthreads();

        float S[4][4] = {};
        #pragma unroll
        for (int d = 0; d < HD; d += 4) {
            float4 ra[4], rb[4];
            #pragma unroll
            for (int i = 0; i < 4; i++) ra[i] = *(const float4*)(sQ + (ty*4 + i) * AT_STRIDE + d);
            #pragma unroll
            for (int e = 0; e < 4; e++) rb[e] = *(const float4*)(sKT + (d + e) * AT_STRIDE + tx*4);
            #pragma unroll
            for (int i = 0; i < 4; i++) {
                float ax = ra[i].x, ay = ra[i].y, az = ra[i].z, aw = ra[i].w;
                S[i][0] = fmaf(ax, rb[0].x, fmaf(ay, rb[1].x, fmaf(az, rb[2].x, fmaf(aw, rb[3].x, S[i][0]))));
                S[i][1] = fmaf(ax, rb[0].y, fmaf(ay, rb[1].y, fmaf(az, rb[2].y, fmaf(aw, rb[3].y, S[i][1]))));
                S[i][2] = fmaf(ax, rb[0].z, fmaf(ay, rb[1].z, fmaf(az, rb[2].z, fmaf(aw, rb[3].z, S[i][2]))));
                S[i][3] = fmaf(ax, rb[0].w, fmaf(ay, rb[1].w, fmaf(az, rb[2].w, fmaf(aw, rb[3].w, S[i][3]))));
            }
        }

        unsigned char pk[4];
        #pragma unroll
        for (int j = 0; j < 4; j++) pk[j] = pad[b * LL + kbase + tx*4 + j];
        #pragma unroll
        for (int i = 0; i < 4; i++) {
            int qg = q0 + ty*4 + i;
            const float* rr = ru + ((size_t)b * LL + qg) * LL + kbase + tx*4;
            float4 r4 = *(const float4*)rr;
            bool okq = (pq[i] == 0);
            float rv[4] = { r4.x, r4.y, r4.z, r4.w };
            #pragma unroll
            for (int j = 0; j < 4; j++) {
                int kg = kbase + tx*4 + j;
                bool ok = ((kg <= qg) || (rv[j] < 0.1f)) && okq && (pk[j] == 0);
                S[i][j] = S[i][j] * 0.125f + (ok ? 0.f : NEGINF);
            }
        }

        #pragma unroll
        for (int i = 0; i < 4; i++) {
            float mx = fmaxf(fmaxf(S[i][0], S[i][1]), fmaxf(S[i][2], S[i][3]));
            #pragma unroll
            for (int o = 1; o < 16; o <<= 1) mx = fmaxf(mx, __shfl_xor_sync(0xffffffffu, mx, o));
            float mn = fmaxf(m_i[i], mx);
            float sc = expf(m_i[i] - mn);
            float p0 = expf(S[i][0] - mn), p1 = expf(S[i][1] - mn);
            float p2 = expf(S[i][2] - mn), p3 = expf(S[i][3] - mn);
            float rs = p0 + p1 + p2 + p3;
            #pragma unroll
            for (int o = 1; o < 16; o <<= 1) rs += __shfl_xor_sync(0xffffffffu, rs, o);
            l_i[i] = l_i[i] * sc + rs;
            m_i[i] = mn;
            #pragma unroll
            for (int j = 0; j < 4; j++) O[i][j] *= sc;
            float* pp = sP + (ty*4 + i) * AT_STRIDE + tx*4;
            pp[0] = p0; pp[1] = p1; pp[2] = p2; pp[3] = p3;
        }
        __syncwarp();

        #pragma unroll
        for (int j = 0; j < 64; j += 4) {
            float4 pa[4], vb[4];
            #pragma unroll
            for (int i = 0; i < 4; i++) pa[i] = *(const float4*)(sP + (ty*4 + i) * AT_STRIDE + j);
            #pragma unroll
            for (int e = 0; e < 4; e++) vb[e] = *(const float4*)(sV + (j + e) * AT_STRIDE + tx*4);
            #pragma unroll
            for (int i = 0; i < 4; i++) {
                float ax = pa[i].x, ay = pa[i].y, az = pa[i].z, aw = pa[i].w;
                O[i][0] = fmaf(ax, vb[0].x, fmaf(ay, vb[1].x, fmaf(az, vb[2].x, fmaf(aw, vb[3].x, O[i][0]))));
                O[i][1] = fmaf(ax, vb[0].y, fmaf(ay, vb[1].y, fmaf(az, vb[2].y, fmaf(aw, vb[3].y, O[i][1]))));
                O[i][2] = fmaf(ax, vb[0].z, fmaf(ay, vb[1].z, fmaf(az, vb[2].z, fmaf(aw, vb[3].z, O[i][2]))));
                O[i][3] = fmaf(ax, vb[0].w, fmaf(ay, vb[1].w, fmaf(az, vb[2].w, fmaf(aw, vb[3].w, O[i][3]))));
            }
        }
    }

    #pragma unroll
    for (int i = 0; i < 4; i++) {
        float inv = 1.f / l_i[i];
        __half2 h0 = __floats2half2_rn(O[i][0] * inv, O[i][1] * inv);
        __half2 h1 = __floats2half2_rn(O[i][2] * inv, O[i][3] * inv);
        __half2* dst = (__half2*)(out + (size_t)(b * LL + q0 + ty*4 + i) * HH + h * HD + tx*4);
        dst[0] = h0; dst[1] = h1;
    }
}

// ---------------- silu(g)*u elementwise -> half ----------------
__global__ void mulh_kernel(const float* __restrict__ a, const float* __restrict__ b,
                            __half* __restrict__ o, int n4) {
    int i = blockIdx.x * blockDim.x + threadIdx.x;
    if (i < n4) {
        float4 x = ((const float4*)a)[i];
        float4 y = ((const float4*)b)[i];
        __half2 h0 = __floats2half2_rn(x.x * y.x, x.y * y.y);
        __half2 h1 = __floats2half2_rn(x.z * y.z, x.w * y.w);
        ((__half2*)o)[i * 2]     = h0;
        ((__half2*)o)[i * 2 + 1] = h1;
    }
}

// ---------------- build xc = concat(hs, time-embed), half ----------------
__global__ void build_xc_kernel(const __half* __restrict__ xnh, const float* __restrict__ tvec,
                                __half* __restrict__ xc) {
    int row = blockIdx.x;
    int b = row >> 9, s = row & 511;
    const __half* src = xnh + (size_t)(b * LL + CC + s) * HH;
    __half* dst = xc + (size_t)row * (HH + TDIM);
    float tb = tvec[b];
    for (int j = threadIdx.x; j < HH + TDIM; j += blockDim.x) {
        __half val;
        if (j < HH) val = src[j];
        else {
            int jj = j - HH;
            int i = (jj < 256) ? jj : (jj - 256);
            float fr = expf(-logf(10000.f) * (float)i / 256.f);
            float a = tb * fr;
            val = __float2half_rn((jj < 256) ? sinf(a) : cosf(a));
        }
        dst[j] = val;
    }
}

// ---------------- rate head stage 2 ----------------
__global__ void rate2_kernel(const float* __restrict__ hsrc, const float* __restrict__ w2,
                             const float* __restrict__ b2, const unsigned char* __restrict__ pad,
                             float* __restrict__ out) {
    int row = blockIdx.x;
    int b = row >> 9, s = row & 511;
    bool pd = pad[b * LL + CC + s] != 0;
    int t = threadIdx.x;
    float a0 = 0.f, a1 = 0.f, a2 = 0.f;
    for (int kk = t; kk < TDIM; kk += 128) {
        float hv = hsrc[(size_t)row * TDIM + kk];
        const float* w = w2 + kk * 3;
        a0 = fmaf(hv, w[0], a0);
        a1 = fmaf(hv, w[1], a1);
        a2 = fmaf(hv, w[2], a2);
    }
    __shared__ float s0[128], s1[128], s2[128];
    s0[t] = a0; s1[t] = a1; s2[t] = a2;
    __syncthreads();
    for (int o = 64; o > 0; o >>= 1) {
        if (t < o) { s0[t] += s0[t+o]; s1[t] += s1[t+o]; s2[t] += s2[t+o]; }
        __syncthreads();
    }
    if (t == 0) {
        float vals[3] = { s0[0] + b2[0], s1[0] + b2[1], s2[0] + b2[2] };
        #pragma unroll
        for (int c = 0; c < 3; c++) {
            float x = vals[c];
            float sp = fmaxf(x, 0.f) + log1pf(expf(-fabsf(x)));
            out[(size_t)row * 3 + c] = pd ? 0.f : sp;
        }
    }
}

// ---------------- softmax over V=32000 (in place) * mask ----------------
__global__ void softmaxV_kernel(float* __restrict__ logits, const unsigned char* __restrict__ pad) {
    __shared__ float red[33];
    int row = blockIdx.x;
    int b = row >> 9, s = row & 511;
    float* lr = logits + (size_t)row * VV;
    int t = threadIdx.x;
    bool pd = pad[b * LL + CC + s] != 0;
    if (pd) {
        for (int i = t; i < VV; i += 256) lr[i] = 0.f;
        return;
    }
    float m = -3.4e38f;
    for (int i = t; i < VV; i += 256) m = fmaxf(m, lr[i]);
    m = block_reduce_max(m, red);
    float sum = 0.f;
    for (int i = t; i < VV; i += 256) {
        float e = expf(lr[i] - m);
        lr[i] = e;
        sum += e;
    }
    sum = block_reduce_sum(sum, red);
    float inv = 1.f / sum;
    for (int i = t; i < VV; i += 256) lr[i] *= inv;
}

// ---------------- host helpers ----------------
static void launch_hgemm(const __half* A, const __half* B, const float* bias,
                         float* Cf, __half* Ch, int M, int N, int K, int acc, int act, int outh) {
    dim3 grid(N / 128, M / 128);
    if (outh)            hgemm_kernel<0,1,1><<<grid,256,HGEMM_SMEM_BYTES>>>(A,B,bias,Cf,Ch,M,N,K);
    else if (acc)        hgemm_kernel<1,0,0><<<grid,256,HGEMM_SMEM_BYTES>>>(A,B,bias,Cf,Ch,M,N,K);
    else if (act)        hgemm_kernel<0,1,0><<<grid,256,HGEMM_SMEM_BYTES>>>(A,B,bias,Cf,Ch,M,N,K);
    else                 hgemm_kernel<0,0,0><<<grid,256,HGEMM_SMEM_BYTES>>>(A,B,bias,Cf,Ch,M,N,K);
}

static void launch_f2h(const float* src, __half* dst, size_t n) {
    int n4 = (int)(n / 4);
    f2h_kernel<<<(n4 + 255) / 256, 256>>>(src, dst, n4);
}

// ---------------- launch ----------------
extern "C" void kernel_launch(void* const* d_in, const int* in_sizes, int n_in,
                              void* d_out, int out_size) {
    const int*   tokens  = (const int*)  d_in[0];
    const float* tvec    = (const float*)d_in[1];
    const int*   ctx     = (const int*)  d_in[3];
    const float* ru      = (const float*)d_in[5];
    const float* embed   = (const float*)d_in[6];
    const float* Wq      = (const float*)d_in[7];
    const float* Wk      = (const float*)d_in[8];
    const float* Wv      = (const float*)d_in[9];
    const float* Wo      = (const float*)d_in[10];
    const float* Wg      = (const float*)d_in[11];
    const float* Wu      = (const float*)d_in[12];
    const float* Wd      = (const float*)d_in[13];
    const float* ln1     = (const float*)d_in[14];
    const float* ln2     = (const float*)d_in[15];
    const float* finln   = (const float*)d_in[16];
    const float* rate_w1 = (const float*)d_in[17];
    const float* rate_b1 = (const float*)d_in[18];
    const float* rate_w2 = (const float*)d_in[19];
    const float* rate_b2 = (const float*)d_in[20];
    const float* ins_w1  = (const float*)d_in[21];
    const float* ins_b1  = (const float*)d_in[22];
    const float* ins_w2  = (const float*)d_in[23];
    const float* ins_b2  = (const float*)d_in[24];
    const float* sub_w1  = (const float*)d_in[25];
    const float* sub_b1  = (const float*)d_in[26];
    const float* sub_w2  = (const float*)d_in[27];
    const float* sub_b2  = (const float*)d_in[28];

    cudaFuncSetAttribute(hgemm_kernel<0,0,0>, cudaFuncAttributeMaxDynamicSharedMemorySize, HGEMM_SMEM_BYTES);
    cudaFuncSetAttribute(hgemm_kernel<1,0,0>, cudaFuncAttributeMaxDynamicSharedMemorySize, HGEMM_SMEM_BYTES);
    cudaFuncSetAttribute(hgemm_kernel<0,1,0>, cudaFuncAttributeMaxDynamicSharedMemorySize, HGEMM_SMEM_BYTES);
    cudaFuncSetAttribute(hgemm_kernel<0,1,1>, cudaFuncAttributeMaxDynamicSharedMemorySize, HGEMM_SMEM_BYTES);
    cudaFuncSetAttribute(hgemm_qkv_kernel,    cudaFuncAttributeMaxDynamicSharedMemorySize, HGEMM_SMEM_BYTES);
    cudaFuncSetAttribute(attn_flash_kernel,   cudaFuncAttributeMaxDynamicSharedMemorySize, ATTN_SMEM_BYTES);

    float *x, *q, *k, *v, *m1, *m2, *hr;
    unsigned char* pad;
    __half *xnh, *atth, *m1h, *xch, *h1h, *wh;
    cudaGetSymbolAddress((void**)&x,    g_x);
    cudaGetSymbolAddress((void**)&q,    g_q);
    cudaGetSymbolAddress((void**)&k,    g_k);
    cudaGetSymbolAddress((void**)&v,    g_v);
    cudaGetSymbolAddress((void**)&m1,   g_m1);
    cudaGetSymbolAddress((void**)&m2,   g_m2);
    cudaGetSymbolAddress((void**)&hr,   g_hr);
    cudaGetSymbolAddress((void**)&pad,  g_pad);
    cudaGetSymbolAddress((void**)&xnh,  g_xnh);
    cudaGetSymbolAddress((void**)&atth, g_atth);
    cudaGetSymbolAddress((void**)&m1h,  g_m1h);
    cudaGetSymbolAddress((void**)&xch,  g_xch);
    cudaGetSymbolAddress((void**)&h1h,  g_h1h);
    cudaGetSymbolAddress((void**)&wh,   g_wh);

    // half weight pool offsets (elements)
    const size_t SZ_ATT = (size_t)NLAYER * HH * HH;       // 4,194,304
    const size_t SZ_MLP = (size_t)NLAYER * HH * FF;       // 16,777,216
    size_t o = 0;
    __half* WqH = wh + o; o += SZ_ATT;
    __half* WkH = wh + o; o += SZ_ATT;
    __half* WvH = wh + o; o += SZ_ATT;
    __half* WoH = wh + o; o += SZ_ATT;
    __half* WgH = wh + o; o += SZ_MLP;
    __half* WuH = wh + o; o += SZ_MLP;
    __half* WdH = wh + o; o += SZ_MLP;
    __half* rw1H = wh + o; o += (size_t)(HH + TDIM) * TDIM;
    __half* iw1H = wh + o; o += (size_t)(HH + TDIM) * HH;
    __half* iw2H = wh + o; o += (size_t)HH * VV;
    __half* sw1H = wh + o; o += (size_t)(HH + TDIM) * HH;
    __half* sw2H = wh + o; o += (size_t)HH * VV;

    // weight conversion (every replay; ~120us of HBM traffic)
    launch_f2h(Wq, WqH, SZ_ATT);
    launch_f2h(Wk, WkH, SZ_ATT);
    launch_f2h(Wv, WvH, SZ_ATT);
    launch_f2h(Wo, WoH, SZ_ATT);
    launch_f2h(Wg, WgH, SZ_MLP);
    launch_f2h(Wu, WuH, SZ_MLP);
    launch_f2h(Wd, WdH, SZ_MLP);
    launch_f2h(rate_w1, rw1H, (size_t)(HH + TDIM) * TDIM);
    launch_f2h(ins_w1,  iw1H, (size_t)(HH + TDIM) * HH);
    launch_f2h(ins_w2,  iw2H, (size_t)HH * VV);
    launch_f2h(sub_w1,  sw1H, (size_t)(HH + TDIM) * HH);
    launch_f2h(sub_w2,  sw2H, (size_t)HH * VV);

    float* out = (float*)d_out;
    const int M = BB * LL;
    const size_t HHsz = (size_t)HH * HH;
    const size_t HFsz = (size_t)HH * FF;

    embed_kernel<<<BB * LL, 256>>>(tokens, ctx, embed, x, pad);

    for (int l = 0; l < NLAYER; l++) {
        rmsnorm_h_kernel<<<M, 256>>>(x, ln1 + (size_t)l * HH, xnh);
        QKVPtrs p { WqH + l * HHsz, WkH + l * HHsz, WvH + l * HHsz, q, k, v };
        hgemm_qkv_kernel<<<dim3(HH/128, M/128, 3), 256, HGEMM_SMEM_BYTES>>>(xnh, p, M, HH, HH);
        rope_kernel<<<M, 1024>>>(q, k);
        attn_flash_kernel<<<dim3(LL/64, NHEAD, BB), 256, ATTN_SMEM_BYTES>>>(q, k, v, ru, pad, atth);
        launch_hgemm(atth, WoH + l * HHsz, nullptr, x, nullptr, M, HH, HH, 1, 0, 0);
        rmsnorm_h_kernel<<<M, 256>>>(x, ln2 + (size_t)l * HH, xnh);
        launch_hgemm(xnh, WgH + l * HFsz, nullptr, m1, nullptr, M, FF, HH, 0, 1, 0);
        launch_hgemm(xnh, WuH + l * HFsz, nullptr, m2, nullptr, M, FF, HH, 0, 0, 0);
        mulh_kernel<<<(M * FF / 4 + 255) / 256, 256>>>(m1, m2, m1h, M * FF / 4);
        launch_hgemm(m1h, WdH + (size_t)l * FF * HH, nullptr, x, nullptr, M, HH, FF, 1, 0, 0);
    }

    rmsnorm_h_kernel<<<M, 256>>>(x, finln, xnh);
    build_xc_kernel<<<BB * SS, 256>>>(xnh, tvec, xch);

    const int BS = BB * SS;
    launch_hgemm(xch, rw1H, rate_b1, hr, nullptr, BS, TDIM, HH + TDIM, 0, 1, 0);
    rate2_kernel<<<BS, 128>>>(hr, rate_w2, rate_b2, pad, out);

    const size_t INS_OFF = (size_t)BS * 3;
    const size_t SUB_OFF = INS_OFF + (size_t)BS * VV;

    launch_hgemm(xch, iw1H, ins_b1, nullptr, h1h, BS, HH, HH + TDIM, 0, 1, 1);
    launch_hgemm(h1h, iw2H, ins_b2, out + INS_OFF, nullptr, BS, VV, HH, 0, 0, 0);
    softmaxV_kernel<<<BS, 256>>>(out + INS_OFF, pad);

    launch_hgemm(xch, sw1H, sub_b1, nullptr, h1h, BS, HH, HH + TDIM, 0, 1, 1);
    launch_hgemm(h1h, sw2H, sub_b2, out + SUB_OFF, nullptr, BS, VV, HH, 0, 0, 0);
    softmaxV_kernel<<<BS, 256>>>(out + SUB_OFF, pad);
}

// round 6
// speedup vs baseline: 8.1221x; 1.3924x over previous
#include <cuda_runtime.h>
#include <cuda_fp16.h>
#include <math.h>
#include <stdint.h>

// ---------------- problem constants ----------------
#define BB 2
#define SS 512
#define CC 512
#define LL 1024
#define HH 1024
#define NHEAD 16
#define HD 64
#define FF 4096
#define NLAYER 4
#define VV 32000
#define TDIM 512
#define NEGINF (-1000000000.0f)

// ---------------- scratch (device globals; no allocs allowed) ----------------
__device__ float g_x  [BB*LL*HH];
__device__ float g_m1 [BB*LL*FF];
__device__ float g_m2 [BB*LL*FF];
__device__ float g_hr [BB*SS*TDIM];
__device__ unsigned char g_pad[BB*LL];
__device__ uint32_t g_mask[BB*LL*32];       // bit k of word (row*32 + k/32): mask ok

// half activations
__device__ __half g_xnh [BB*LL*HH];
__device__ __half g_qh  [BB*LL*HH];
__device__ __half g_kh  [BB*LL*HH];
__device__ __half g_vh  [BB*LL*HH];
__device__ __half g_atth[BB*LL*HH];
__device__ __half g_m1h [BB*LL*FF];
__device__ __half g_xch [BB*SS*(HH+TDIM)];
__device__ __half g_h1h [BB*SS*HH];

// half weight pool
#define WH_TOTAL 136577024
__device__ __half g_wh[WH_TOTAL];

// ---------------- block reductions ----------------
__device__ __forceinline__ float block_reduce_sum(float v, float* red) {
    int t = threadIdx.x, lane = t & 31, w = t >> 5;
    #pragma unroll
    for (int o = 16; o > 0; o >>= 1) v += __shfl_xor_sync(0xffffffffu, v, o);
    if (lane == 0) red[w] = v;
    __syncthreads();
    int nw = (blockDim.x + 31) >> 5;
    float r = (t < nw) ? red[t] : 0.f;
    if (w == 0) {
        #pragma unroll
        for (int o = 16; o > 0; o >>= 1) r += __shfl_xor_sync(0xffffffffu, r, o);
        if (t == 0) red[0] = r;
    }
    __syncthreads();
    float out = red[0];
    __syncthreads();
    return out;
}

__device__ __forceinline__ float block_reduce_max(float v, float* red) {
    int t = threadIdx.x, lane = t & 31, w = t >> 5;
    #pragma unroll
    for (int o = 16; o > 0; o >>= 1) v = fmaxf(v, __shfl_xor_sync(0xffffffffu, v, o));
    if (lane == 0) red[w] = v;
    __syncthreads();
    int nw = (blockDim.x + 31) >> 5;
    float r = (t < nw) ? red[t] : -3.4e38f;
    if (w == 0) {
        #pragma unroll
        for (int o = 16; o > 0; o >>= 1) r = fmaxf(r, __shfl_xor_sync(0xffffffffu, r, o));
        if (t == 0) red[0] = r;
    }
    __syncthreads();
    float out = red[0];
    __syncthreads();
    return out;
}

// ---------------- async copy / ldmatrix helpers ----------------
__device__ __forceinline__ void cp_async16(void* dst, const void* src) {
    uint32_t d = (uint32_t)__cvta_generic_to_shared(dst);
    asm volatile("cp.async.cg.shared.global [%0], [%1], 16;\n" :: "r"(d), "l"(src));
}
#define CP_ASYNC_COMMIT() asm volatile("cp.async.commit_group;\n" ::)
#define CP_ASYNC_WAIT(N)  asm volatile("cp.async.wait_group %0;\n" :: "n"(N))

__device__ __forceinline__ void ldsm_x4(uint32_t& r0, uint32_t& r1, uint32_t& r2, uint32_t& r3, uint32_t addr) {
    asm volatile("ldmatrix.sync.aligned.m8n8.x4.shared.b16 {%0,%1,%2,%3}, [%4];"
        : "=r"(r0), "=r"(r1), "=r"(r2), "=r"(r3) : "r"(addr));
}
__device__ __forceinline__ void ldsm_x2(uint32_t& r0, uint32_t& r1, uint32_t addr) {
    asm volatile("ldmatrix.sync.aligned.m8n8.x2.shared.b16 {%0,%1}, [%2];"
        : "=r"(r0), "=r"(r1) : "r"(addr));
}
__device__ __forceinline__ void ldsm_x2t(uint32_t& r0, uint32_t& r1, uint32_t addr) {
    asm volatile("ldmatrix.sync.aligned.m8n8.x2.trans.shared.b16 {%0,%1}, [%2];"
        : "=r"(r0), "=r"(r1) : "r"(addr));
}
__device__ __forceinline__ void mma_f16(float* c, uint32_t a0, uint32_t a1, uint32_t a2, uint32_t a3,
                                        uint32_t b0, uint32_t b1) {
    asm volatile(
        "mma.sync.aligned.m16n8k16.row.col.f32.f16.f16.f32 "
        "{%0,%1,%2,%3}, {%4,%5,%6,%7}, {%8,%9}, {%0,%1,%2,%3};"
        : "+f"(c[0]), "+f"(c[1]), "+f"(c[2]), "+f"(c[3])
        : "r"(a0), "r"(a1), "r"(a2), "r"(a3), "r"(b0), "r"(b1));
}

// ---------------- fp16 tensor-core GEMM, cp.async 3-stage pipelined ----------------
#define HA_STRIDE 40
#define HB_STRIDE 136
#define HA_STAGE (128*HA_STRIDE)
#define HB_STAGE (32*HB_STRIDE)
#define HGEMM_SMEM_BYTES ((3*(HA_STAGE + HB_STAGE)) * 2)

template<int ACC, int ACT, int OUTH>
__device__ __forceinline__ void hgemm_core(const __half* __restrict__ A, const __half* __restrict__ Bm,
                                           const float* __restrict__ bias,
                                           float* __restrict__ Cf, __half* __restrict__ Ch,
                                           int M, int N, int K, __half* sm) {
    __half* sA = sm;
    __half* sB = sm + 3 * HA_STAGE;
    const int tid = threadIdx.x;
    const int lane = tid & 31;
    const int warp = tid >> 5;
    const int warp_m = warp >> 2;
    const int warp_n = warp & 3;
    const int g  = lane >> 2;
    const int t4 = lane & 3;
    const int bm = blockIdx.y;
    const int bn = blockIdx.x;

    float acc[4][4][4] = {};

    const int a_row = tid >> 1;
    const int a_col = (tid & 1) * 16;
    const int b_row = tid >> 3;
    const int b_col = (tid & 7) * 16;
    const __half* Agp = A  + (size_t)(bm * 128 + a_row) * K + a_col;
    const __half* Bgp = Bm + (size_t)b_row * N + (size_t)bn * 128 + b_col;

    const int KT = K >> 5;

    uint32_t sA_b = (uint32_t)__cvta_generic_to_shared(sA);
    uint32_t sB_b = (uint32_t)__cvta_generic_to_shared(sB);
    uint32_t aBase = sA_b + (uint32_t)(((warp_m * 64 + (lane & 15)) * HA_STRIDE + (lane >> 4) * 8) * 2);
    uint32_t bBase = sB_b + (uint32_t)((((lane & 15)) * HB_STRIDE + warp_n * 32) * 2);

    // prologue: stages 0,1
    #pragma unroll
    for (int s = 0; s < 2; s++) {
        __half* da = sA + s * HA_STAGE + a_row * HA_STRIDE + a_col;
        __half* db = sB + s * HB_STAGE + b_row * HB_STRIDE + b_col;
        const __half* ga = Agp + s * 32;
        const __half* gb = Bgp + (size_t)s * 32 * N;
        cp_async16(da,     ga);
        cp_async16(da + 8, ga + 8);
        cp_async16(db,     gb);
        cp_async16(db + 8, gb + 8);
        CP_ASYNC_COMMIT();
    }

    int slot_next = 2;
    for (int kt = 0; kt < KT; kt++) {
        if (kt + 2 < KT) {
            __half* da = sA + slot_next * HA_STAGE + a_row * HA_STRIDE + a_col;
            __half* db = sB + slot_next * HB_STAGE + b_row * HB_STRIDE + b_col;
            const __half* ga = Agp + (kt + 2) * 32;
            const __half* gb = Bgp + (size_t)(kt + 2) * 32 * N;
            cp_async16(da,     ga);
            cp_async16(da + 8, ga + 8);
            cp_async16(db,     gb);
            cp_async16(db + 8, gb + 8);
        }
        CP_ASYNC_COMMIT();
        CP_ASYNC_WAIT(2);
        __syncthreads();

        int slot = (slot_next + 1) % 3;   // == kt % 3
        slot_next = (slot_next + 1) % 3;  // advance ring
        // note: slot computed so that kt%3 is the ready stage
        slot = kt % 3;
        slot_next = (kt + 3) % 3 == slot ? (kt + 3) % 3 : (kt + 3) % 3; // = slot of kt+3
        slot_next = (kt + 3) % 3;

        uint32_t aSt = aBase + (uint32_t)(slot * HA_STAGE * 2);
        uint32_t bSt = bBase + (uint32_t)(slot * HB_STAGE * 2);

        #pragma unroll
        for (int ks = 0; ks < 2; ks++) {
            uint32_t af[4][4], bf[4][2];
            #pragma unroll
            for (int mt = 0; mt < 4; mt++)
                ldsm_x4(af[mt][0], af[mt][1], af[mt][2], af[mt][3],
                        aSt + (uint32_t)(mt * 16 * HA_STRIDE * 2 + ks * 32));
            #pragma unroll
            for (int nt = 0; nt < 4; nt++)
                ldsm_x2t(bf[nt][0], bf[nt][1],
                         bSt + (uint32_t)(ks * 16 * HB_STRIDE * 2 + nt * 16));
            #pragma unroll
            for (int mt = 0; mt < 4; mt++)
                #pragma unroll
                for (int nt = 0; nt < 4; nt++)
                    mma_f16(acc[mt][nt], af[mt][0], af[mt][1], af[mt][2], af[mt][3],
                            bf[nt][0], bf[nt][1]);
        }
        __syncthreads();
    }

    #pragma unroll
    for (int mt = 0; mt < 4; mt++) {
        int row0 = bm * 128 + warp_m * 64 + mt * 16 + g;
        #pragma unroll
        for (int nt = 0; nt < 4; nt++) {
            int col0 = bn * 128 + warp_n * 32 + nt * 8 + t4 * 2;
            #pragma unroll
            for (int f = 0; f < 4; f++) {
                int r = row0 + ((f & 2) ? 8 : 0);
                int c = col0 + (f & 1);
                float vv = acc[mt][nt][f];
                if (bias) vv += bias[c];
                if (ACT == 1) vv = vv / (1.f + expf(-vv));
                size_t idx = (size_t)r * N + c;
                if (OUTH) {
                    Ch[idx] = __float2half_rn(vv);
                } else {
                    if (ACC) vv += Cf[idx];
                    Cf[idx] = vv;
                }
            }
        }
    }
}

template<int ACC, int ACT, int OUTH>
__global__ __launch_bounds__(256, 2)
void hgemm_kernel(const __half* __restrict__ A, const __half* __restrict__ Bm,
                  const float* __restrict__ bias, float* __restrict__ Cf, __half* __restrict__ Ch,
                  int M, int N, int K) {
    extern __shared__ __half smh[];
    hgemm_core<ACC, ACT, OUTH>(A, Bm, bias, Cf, Ch, M, N, K, smh);
}

struct QKVPtrsH { const __half *Bq, *Bk, *Bv; __half *Cq, *Ck, *Cv; };

__global__ __launch_bounds__(256, 2)
void hgemm_qkv_kernel(const __half* __restrict__ A, QKVPtrsH p, int M, int N, int K) {
    extern __shared__ __half smh[];
    const __half* Bm = (blockIdx.z == 0) ? p.Bq : (blockIdx.z == 1) ? p.Bk : p.Bv;
    __half*       Cm = (blockIdx.z == 0) ? p.Cq : (blockIdx.z == 1) ? p.Ck : p.Cv;
    hgemm_core<0, 0, 1>(A, Bm, nullptr, nullptr, Cm, M, N, K, smh);
}

// ---------------- fp32 -> fp16 conversion ----------------
__global__ void f2h_kernel(const float* __restrict__ src, __half* __restrict__ dst, int n4) {
    int i = blockIdx.x * blockDim.x + threadIdx.x;
    if (i < n4) {
        float4 v = ((const float4*)src)[i];
        ((__half2*)dst)[i * 2]     = __floats2half2_rn(v.x, v.y);
        ((__half2*)dst)[i * 2 + 1] = __floats2half2_rn(v.z, v.w);
    }
}

// ---------------- embedding gather + pad flags ----------------
__global__ void embed_kernel(const int* __restrict__ tokens, const int* __restrict__ ctx,
                             const float* __restrict__ embed, float* __restrict__ x,
                             unsigned char* __restrict__ pad) {
    int row = blockIdx.x;
    int b = row >> 10, l = row & 1023;
    int tok = (l < CC) ? ctx[b * CC + l] : tokens[b * SS + (l - CC)];
    if (threadIdx.x == 0) pad[row] = (tok == 0) ? 1 : 0;
    const float4* e = (const float4*)(embed + (size_t)tok * HH);
    float4* xr = (float4*)(x + (size_t)row * HH);
    xr[threadIdx.x] = e[threadIdx.x];
}

// ---------------- mask bitfield: one warp per query row ----------------
__global__ void mask_kernel(const float* __restrict__ ru, const unsigned char* __restrict__ pad,
                            uint32_t* __restrict__ mw) {
    int gw = (blockIdx.x * blockDim.x + threadIdx.x) >> 5;   // row index b*LL + q
    int lane = threadIdx.x & 31;
    int b = gw >> 10, qi = gw & 1023;
    bool padq = pad[gw] != 0;
    const float* rr = ru + (size_t)b * LL * LL + (size_t)qi * LL;
    for (int k0 = 0; k0 < LL; k0 += 32) {
        int kg = k0 + lane;
        bool ok = ((kg <= qi) || (rr[kg] < 0.1f)) && !padq && (pad[b * LL + kg] == 0);
        uint32_t wv = __ballot_sync(0xffffffffu, ok);
        if (lane == 0) mw[gw * 32 + (k0 >> 5)] = wv;
    }
}

// ---------------- rmsnorm (fp32 in, fp16 out) ----------------
__global__ void rmsnorm_h_kernel(const float* __restrict__ x, const float* __restrict__ g,
                                 __half* __restrict__ out) {
    __shared__ float red[33];
    int row = blockIdx.x;
    int t = threadIdx.x;
    const float4* xr = (const float4*)(x + (size_t)row * HH);
    float4 v = xr[t];
    float s = v.x*v.x + v.y*v.y + v.z*v.z + v.w*v.w;
    s = block_reduce_sum(s, red);
    float rs = rsqrtf(s / (float)HH + 1e-6f);
    float4 gg = ((const float4*)g)[t];
    __half2* o = (__half2*)(out + (size_t)row * HH);
    o[t * 2]     = __floats2half2_rn(v.x * rs * gg.x, v.y * rs * gg.y);
    o[t * 2 + 1] = __floats2half2_rn(v.z * rs * gg.z, v.w * rs * gg.w);
}

// ---------------- RoPE on half (in-place on q and k) ----------------
__global__ void rope_h_kernel(__half* __restrict__ q, __half* __restrict__ k) {
    int row = blockIdx.x;
    int p = row & 1023;
    int t = threadIdx.x;
    int d = t & 63;
    int i = d & 31;
    float invf = expf(-logf(10000.f) * (float)i / 32.f);
    float ang = (float)p * invf;
    float c = cosf(ang), s = sinf(ang);
    size_t idx = (size_t)row * HH + t;
    size_t idx2 = (d < 32) ? (idx + 32) : (idx - 32);
    float qd = __half2float(q[idx]), kd = __half2float(k[idx]);
    float qo = (d < 32) ? -__half2float(q[idx2]) : __half2float(q[idx2]);
    float ko = (d < 32) ? -__half2float(k[idx2]) : __half2float(k[idx2]);
    __syncthreads();
    q[idx] = __float2half_rn(qd * c + qo * s);
    k[idx] = __float2half_rn(kd * c + ko * s);
}

// ---------------- tensor-core flash attention ----------------
// grid (LL/64, NHEAD, BB), 128 threads (4 warps). Warp w: q rows w*16..w*16+15.
#define AQ_STRIDE 72

__global__ __launch_bounds__(128)
void attn_mma_kernel(const __half* __restrict__ qh, const __half* __restrict__ kh,
                     const __half* __restrict__ vh, const uint32_t* __restrict__ maskw,
                     __half* __restrict__ out) {
    __shared__ __half sQ[64 * AQ_STRIDE];
    __shared__ __half sK[64 * AQ_STRIDE];
    __shared__ __half sV[64 * AQ_STRIDE];

    const int qt = blockIdx.x, h = blockIdx.y, b = blockIdx.z;
    const int t = threadIdx.x, lane = t & 31, w = t >> 5;
    const int g = lane >> 2, t4 = lane & 3;
    const int q0 = qt * 64;

    // load Q tile (64 x 64 halfs)
    {
        int r = t >> 1;
        int cc = (t & 1) * 32;
        const __half* src = qh + (size_t)(b * LL + q0 + r) * HH + h * HD + cc;
        __half* dst = sQ + r * AQ_STRIDE + cc;
        #pragma unroll
        for (int j = 0; j < 4; j++)
            *(float4*)(dst + j * 8) = *(const float4*)(src + j * 8);
    }
    __syncthreads();

    uint32_t sQ_b = (uint32_t)__cvta_generic_to_shared(sQ);
    uint32_t sK_b = (uint32_t)__cvta_generic_to_shared(sK);
    uint32_t sV_b = (uint32_t)__cvta_generic_to_shared(sV);

    // Q fragments: 4 k-steps
    uint32_t qf[4][4];
    {
        uint32_t base = sQ_b + (uint32_t)(((w * 16 + (lane & 15)) * AQ_STRIDE + (lane >> 4) * 8) * 2);
        #pragma unroll
        for (int ks = 0; ks < 4; ks++)
            ldsm_x4(qf[ks][0], qf[ks][1], qf[ks][2], qf[ks][3], base + ks * 32);
    }

    const int l15 = lane & 15;
    uint32_t kBase = sK_b + (uint32_t)(((l15 & 7) * AQ_STRIDE + (l15 >> 3) * 8) * 2);
    uint32_t vBase = sV_b + (uint32_t)((l15 * AQ_STRIDE) * 2);

    float m0 = -3.4e38f, m1 = -3.4e38f, l0 = 0.f, l1 = 0.f;
    float O[8][4] = {};

    const int mrow0 = (b * LL + q0 + w * 16 + g) * 32;
    const int mrow1 = mrow0 + 8 * 32;

    for (int c = 0; c < LL / 64; c++) {
        const int kbase = c * 64;
        __syncthreads();
        {
            int r = t >> 1;
            int cc = (t & 1) * 32;
            const __half* ksrc = kh + (size_t)(b * LL + kbase + r) * HH + h * HD + cc;
            const __half* vsrc = vh + (size_t)(b * LL + kbase + r) * HH + h * HD + cc;
            __half* kdst = sK + r * AQ_STRIDE + cc;
            __half* vdst = sV + r * AQ_STRIDE + cc;
            #pragma unroll
            for (int j = 0; j < 4; j++) {
                *(float4*)(kdst + j * 8) = *(const float4*)(ksrc + j * 8);
                *(float4*)(vdst + j * 8) = *(const float4*)(vsrc + j * 8);
            }
        }
        __syncthreads();

        // S = Q K^T : 8 n-tiles x 4 k-steps
        float S[8][4] = {};
        #pragma unroll
        for (int ks = 0; ks < 4; ks++) {
            #pragma unroll
            for (int nt = 0; nt < 8; nt++) {
                uint32_t b0, b1;
                ldsm_x2(b0, b1, kBase + (uint32_t)((nt * 8 * AQ_STRIDE) * 2 + ks * 32));
                mma_f16(S[nt], qf[ks][0], qf[ks][1], qf[ks][2], qf[ks][3], b0, b1);
            }
        }

        // mask
        uint32_t mw00 = maskw[mrow0 + (kbase >> 5)];
        uint32_t mw01 = maskw[mrow0 + (kbase >> 5) + 1];
        uint32_t mw10 = maskw[mrow1 + (kbase >> 5)];
        uint32_t mw11 = maskw[mrow1 + (kbase >> 5) + 1];
        #pragma unroll
        for (int nt = 0; nt < 8; nt++) {
            int bp = nt * 8 + 2 * t4;
            uint32_t w0 = (nt < 4) ? mw00 : mw01;
            uint32_t w1 = (nt < 4) ? mw10 : mw11;
            int sh = bp & 31;
            S[nt][0] = S[nt][0] * 0.125f + (((w0 >> sh) & 1u)       ? 0.f : NEGINF);
            S[nt][1] = S[nt][1] * 0.125f + (((w0 >> (sh + 1)) & 1u) ? 0.f : NEGINF);
            S[nt][2] = S[nt][2] * 0.125f + (((w1 >> sh) & 1u)       ? 0.f : NEGINF);
            S[nt][3] = S[nt][3] * 0.125f + (((w1 >> (sh + 1)) & 1u) ? 0.f : NEGINF);
        }

        // online softmax
        float mx0 = -3.4e38f, mx1 = -3.4e38f;
        #pragma unroll
        for (int nt = 0; nt < 8; nt++) {
            mx0 = fmaxf(mx0, fmaxf(S[nt][0], S[nt][1]));
            mx1 = fmaxf(mx1, fmaxf(S[nt][2], S[nt][3]));
        }
        mx0 = fmaxf(mx0, __shfl_xor_sync(0xffffffffu, mx0, 1));
        mx0 = fmaxf(mx0, __shfl_xor_sync(0xffffffffu, mx0, 2));
        mx1 = fmaxf(mx1, __shfl_xor_sync(0xffffffffu, mx1, 1));
        mx1 = fmaxf(mx1, __shfl_xor_sync(0xffffffffu, mx1, 2));
        float nm0 = fmaxf(m0, mx0), nm1 = fmaxf(m1, mx1);
        float sc0 = expf(m0 - nm0), sc1 = expf(m1 - nm1);

        uint32_t P[8][2];
        float rs0 = 0.f, rs1 = 0.f;
        #pragma unroll
        for (int nt = 0; nt < 8; nt++) {
            float p00 = expf(S[nt][0] - nm0), p01 = expf(S[nt][1] - nm0);
            float p10 = expf(S[nt][2] - nm1), p11 = expf(S[nt][3] - nm1);
            rs0 += p00 + p01; rs1 += p10 + p11;
            __half2 h0 = __floats2half2_rn(p00, p01);
            __half2 h1 = __floats2half2_rn(p10, p11);
            P[nt][0] = *(uint32_t*)&h0;
            P[nt][1] = *(uint32_t*)&h1;
        }
        rs0 += __shfl_xor_sync(0xffffffffu, rs0, 1);
        rs0 += __shfl_xor_sync(0xffffffffu, rs0, 2);
        rs1 += __shfl_xor_sync(0xffffffffu, rs1, 1);
        rs1 += __shfl_xor_sync(0xffffffffu, rs1, 2);
        l0 = l0 * sc0 + rs0; l1 = l1 * sc1 + rs1;
        m0 = nm0; m1 = nm1;
        #pragma unroll
        for (int nt = 0; nt < 8; nt++) {
            O[nt][0] *= sc0; O[nt][1] *= sc0;
            O[nt][2] *= sc1; O[nt][3] *= sc1;
        }

        // O += P @ V : 4 k-steps over keys
        #pragma unroll
        for (int j = 0; j < 4; j++) {
            uint32_t a0 = P[2*j][0], a1 = P[2*j][1], a2 = P[2*j+1][0], a3 = P[2*j+1][1];
            #pragma unroll
            for (int nv = 0; nv < 8; nv++) {
                uint32_t b0, b1;
                ldsm_x2t(b0, b1, vBase + (uint32_t)((j * 16 * AQ_STRIDE + nv * 8) * 2));
                mma_f16(O[nv], a0, a1, a2, a3, b0, b1);
            }
        }
    }

    float inv0 = 1.f / l0, inv1 = 1.f / l1;
    int row0 = b * LL + q0 + w * 16 + g;
    int row1 = row0 + 8;
    #pragma unroll
    for (int nv = 0; nv < 8; nv++) {
        __half2 o0 = __floats2half2_rn(O[nv][0] * inv0, O[nv][1] * inv0);
        __half2 o1 = __floats2half2_rn(O[nv][2] * inv1, O[nv][3] * inv1);
        *(__half2*)(out + (size_t)row0 * HH + h * HD + nv * 8 + 2 * t4) = o0;
        *(__half2*)(out + (size_t)row1 * HH + h * HD + nv * 8 + 2 * t4) = o1;
    }
}

// ---------------- silu(g)*u elementwise -> half ----------------
__global__ void mulh_kernel(const float* __restrict__ a, const float* __restrict__ b,
                            __half* __restrict__ o, int n4) {
    int i = blockIdx.x * blockDim.x + threadIdx.x;
    if (i < n4) {
        float4 x = ((const float4*)a)[i];
        float4 y = ((const float4*)b)[i];
        ((__half2*)o)[i * 2]     = __floats2half2_rn(x.x * y.x, x.y * y.y);
        ((__half2*)o)[i * 2 + 1] = __floats2half2_rn(x.z * y.z, x.w * y.w);
    }
}

// ---------------- build xc = concat(hs, time-embed), half ----------------
__global__ void build_xc_kernel(const __half* __restrict__ xnh, const float* __restrict__ tvec,
                                __half* __restrict__ xc) {
    int row = blockIdx.x;
    int b = row >> 9, s = row & 511;
    const __half* src = xnh + (size_t)(b * LL + CC + s) * HH;
    __half* dst = xc + (size_t)row * (HH + TDIM);
    float tb = tvec[b];
    for (int j = threadIdx.x; j < HH + TDIM; j += blockDim.x) {
        __half val;
        if (j < HH) val = src[j];
        else {
            int jj = j - HH;
            int i = (jj < 256) ? jj : (jj - 256);
            float fr = expf(-logf(10000.f) * (float)i / 256.f);
            float a = tb * fr;
            val = __float2half_rn((jj < 256) ? sinf(a) : cosf(a));
        }
        dst[j] = val;
    }
}

// ---------------- rate head stage 2 ----------------
__global__ void rate2_kernel(const float* __restrict__ hsrc, const float* __restrict__ w2,
                             const float* __restrict__ b2, const unsigned char* __restrict__ pad,
                             float* __restrict__ out) {
    int row = blockIdx.x;
    int b = row >> 9, s = row & 511;
    bool pd = pad[b * LL + CC + s] != 0;
    int t = threadIdx.x;
    float a0 = 0.f, a1 = 0.f, a2 = 0.f;
    for (int kk = t; kk < TDIM; kk += 128) {
        float hv = hsrc[(size_t)row * TDIM + kk];
        const float* w = w2 + kk * 3;
        a0 = fmaf(hv, w[0], a0);
        a1 = fmaf(hv, w[1], a1);
        a2 = fmaf(hv, w[2], a2);
    }
    __shared__ float s0[128], s1[128], s2[128];
    s0[t] = a0; s1[t] = a1; s2[t] = a2;
    __syncthreads();
    for (int o = 64; o > 0; o >>= 1) {
        if (t < o) { s0[t] += s0[t+o]; s1[t] += s1[t+o]; s2[t] += s2[t+o]; }
        __syncthreads();
    }
    if (t == 0) {
        float vals[3] = { s0[0] + b2[0], s1[0] + b2[1], s2[0] + b2[2] };
        #pragma unroll
        for (int c = 0; c < 3; c++) {
            float x = vals[c];
            float sp = fmaxf(x, 0.f) + log1pf(expf(-fabsf(x)));
            out[(size_t)row * 3 + c] = pd ? 0.f : sp;
        }
    }
}

// ---------------- softmax over V=32000 (in place) * mask ----------------
__global__ void softmaxV_kernel(float* __restrict__ logits, const unsigned char* __restrict__ pad) {
    __shared__ float red[33];
    int row = blockIdx.x;
    int b = row >> 9, s = row & 511;
    float* lr = logits + (size_t)row * VV;
    int t = threadIdx.x;
    bool pd = pad[b * LL + CC + s] != 0;
    if (pd) {
        for (int i = t; i < VV; i += 256) lr[i] = 0.f;
        return;
    }
    float m = -3.4e38f;
    for (int i = t; i < VV; i += 256) m = fmaxf(m, lr[i]);
    m = block_reduce_max(m, red);
    float sum = 0.f;
    for (int i = t; i < VV; i += 256) {
        float e = expf(lr[i] - m);
        lr[i] = e;
        sum += e;
    }
    sum = block_reduce_sum(sum, red);
    float inv = 1.f / sum;
    for (int i = t; i < VV; i += 256) lr[i] *= inv;
}

// ---------------- host helpers ----------------
static void launch_hgemm(const __half* A, const __half* B, const float* bias,
                         float* Cf, __half* Ch, int M, int N, int K, int acc, int act, int outh) {
    dim3 grid(N / 128, M / 128);
    if (outh)            hgemm_kernel<0,1,1><<<grid,256,HGEMM_SMEM_BYTES>>>(A,B,bias,Cf,Ch,M,N,K);
    else if (acc)        hgemm_kernel<1,0,0><<<grid,256,HGEMM_SMEM_BYTES>>>(A,B,bias,Cf,Ch,M,N,K);
    else if (act)        hgemm_kernel<0,1,0><<<grid,256,HGEMM_SMEM_BYTES>>>(A,B,bias,Cf,Ch,M,N,K);
    else                 hgemm_kernel<0,0,0><<<grid,256,HGEMM_SMEM_BYTES>>>(A,B,bias,Cf,Ch,M,N,K);
}

static void launch_f2h(const float* src, __half* dst, size_t n) {
    int n4 = (int)(n / 4);
    f2h_kernel<<<(n4 + 255) / 256, 256>>>(src, dst, n4);
}

// ---------------- launch ----------------
extern "C" void kernel_launch(void* const* d_in, const int* in_sizes, int n_in,
                              void* d_out, int out_size) {
    const int*   tokens  = (const int*)  d_in[0];
    const float* tvec    = (const float*)d_in[1];
    const int*   ctx     = (const int*)  d_in[3];
    const float* ru      = (const float*)d_in[5];
    const float* embed   = (const float*)d_in[6];
    const float* Wq      = (const float*)d_in[7];
    const float* Wk      = (const float*)d_in[8];
    const float* Wv      = (const float*)d_in[9];
    const float* Wo      = (const float*)d_in[10];
    const float* Wg      = (const float*)d_in[11];
    const float* Wu      = (const float*)d_in[12];
    const float* Wd      = (const float*)d_in[13];
    const float* ln1     = (const float*)d_in[14];
    const float* ln2     = (const float*)d_in[15];
    const float* finln   = (const float*)d_in[16];
    const float* rate_w1 = (const float*)d_in[17];
    const float* rate_b1 = (const float*)d_in[18];
    const float* rate_w2 = (const float*)d_in[19];
    const float* rate_b2 = (const float*)d_in[20];
    const float* ins_w1  = (const float*)d_in[21];
    const float* ins_b1  = (const float*)d_in[22];
    const float* ins_w2  = (const float*)d_in[23];
    const float* ins_b2  = (const float*)d_in[24];
    const float* sub_w1  = (const float*)d_in[25];
    const float* sub_b1  = (const float*)d_in[26];
    const float* sub_w2  = (const float*)d_in[27];
    const float* sub_b2  = (const float*)d_in[28];

    cudaFuncSetAttribute(hgemm_kernel<0,0,0>, cudaFuncAttributeMaxDynamicSharedMemorySize, HGEMM_SMEM_BYTES);
    cudaFuncSetAttribute(hgemm_kernel<1,0,0>, cudaFuncAttributeMaxDynamicSharedMemorySize, HGEMM_SMEM_BYTES);
    cudaFuncSetAttribute(hgemm_kernel<0,1,0>, cudaFuncAttributeMaxDynamicSharedMemorySize, HGEMM_SMEM_BYTES);
    cudaFuncSetAttribute(hgemm_kernel<0,1,1>, cudaFuncAttributeMaxDynamicSharedMemorySize, HGEMM_SMEM_BYTES);
    cudaFuncSetAttribute(hgemm_qkv_kernel,    cudaFuncAttributeMaxDynamicSharedMemorySize, HGEMM_SMEM_BYTES);

    float *x, *m1, *m2, *hr;
    unsigned char* pad;
    uint32_t* maskw;
    __half *xnh, *qh, *kh, *vh, *atth, *m1h, *xch, *h1h, *wh;
    cudaGetSymbolAddress((void**)&x,    g_x);
    cudaGetSymbolAddress((void**)&m1,   g_m1);
    cudaGetSymbolAddress((void**)&m2,   g_m2);
    cudaGetSymbolAddress((void**)&hr,   g_hr);
    cudaGetSymbolAddress((void**)&pad,  g_pad);
    cudaGetSymbolAddress((void**)&maskw,g_mask);
    cudaGetSymbolAddress((void**)&xnh,  g_xnh);
    cudaGetSymbolAddress((void**)&qh,   g_qh);
    cudaGetSymbolAddress((void**)&kh,   g_kh);
    cudaGetSymbolAddress((void**)&vh,   g_vh);
    cudaGetSymbolAddress((void**)&atth, g_atth);
    cudaGetSymbolAddress((void**)&m1h,  g_m1h);
    cudaGetSymbolAddress((void**)&xch,  g_xch);
    cudaGetSymbolAddress((void**)&h1h,  g_h1h);
    cudaGetSymbolAddress((void**)&wh,   g_wh);

    const size_t SZ_ATT = (size_t)NLAYER * HH * HH;
    const size_t SZ_MLP = (size_t)NLAYER * HH * FF;
    size_t o = 0;
    __half* WqH = wh + o; o += SZ_ATT;
    __half* WkH = wh + o; o += SZ_ATT;
    __half* WvH = wh + o; o += SZ_ATT;
    __half* WoH = wh + o; o += SZ_ATT;
    __half* WgH = wh + o; o += SZ_MLP;
    __half* WuH = wh + o; o += SZ_MLP;
    __half* WdH = wh + o; o += SZ_MLP;
    __half* rw1H = wh + o; o += (size_t)(HH + TDIM) * TDIM;
    __half* iw1H = wh + o; o += (size_t)(HH + TDIM) * HH;
    __half* iw2H = wh + o; o += (size_t)HH * VV;
    __half* sw1H = wh + o; o += (size_t)(HH + TDIM) * HH;
    __half* sw2H = wh + o; o += (size_t)HH * VV;

    launch_f2h(Wq, WqH, SZ_ATT);
    launch_f2h(Wk, WkH, SZ_ATT);
    launch_f2h(Wv, WvH, SZ_ATT);
    launch_f2h(Wo, WoH, SZ_ATT);
    launch_f2h(Wg, WgH, SZ_MLP);
    launch_f2h(Wu, WuH, SZ_MLP);
    launch_f2h(Wd, WdH, SZ_MLP);
    launch_f2h(rate_w1, rw1H, (size_t)(HH + TDIM) * TDIM);
    launch_f2h(ins_w1,  iw1H, (size_t)(HH + TDIM) * HH);
    launch_f2h(ins_w2,  iw2H, (size_t)HH * VV);
    launch_f2h(sub_w1,  sw1H, (size_t)(HH + TDIM) * HH);
    launch_f2h(sub_w2,  sw2H, (size_t)HH * VV);

    float* out = (float*)d_out;
    const int M = BB * LL;
    const size_t HHsz = (size_t)HH * HH;
    const size_t HFsz = (size_t)HH * FF;

    embed_kernel<<<BB * LL, 256>>>(tokens, ctx, embed, x, pad);
    mask_kernel<<<BB * LL / 8, 256>>>(ru, pad, maskw);

    for (int l = 0; l < NLAYER; l++) {
        rmsnorm_h_kernel<<<M, 256>>>(x, ln1 + (size_t)l * HH, xnh);
        QKVPtrsH p { WqH + l * HHsz, WkH + l * HHsz, WvH + l * HHsz, qh, kh, vh };
        hgemm_qkv_kernel<<<dim3(HH/128, M/128, 3), 256, HGEMM_SMEM_BYTES>>>(xnh, p, M, HH, HH);
        rope_h_kernel<<<M, 1024>>>(qh, kh);
        attn_mma_kernel<<<dim3(LL/64, NHEAD, BB), 128>>>(qh, kh, vh, maskw, atth);
        launch_hgemm(atth, WoH + l * HHsz, nullptr, x, nullptr, M, HH, HH, 1, 0, 0);
        rmsnorm_h_kernel<<<M, 256>>>(x, ln2 + (size_t)l * HH, xnh);
        launch_hgemm(xnh, WgH + l * HFsz, nullptr, m1, nullptr, M, FF, HH, 0, 1, 0);
        launch_hgemm(xnh, WuH + l * HFsz, nullptr, m2, nullptr, M, FF, HH, 0, 0, 0);
        mulh_kernel<<<(M * FF / 4 + 255) / 256, 256>>>(m1, m2, m1h, M * FF / 4);
        launch_hgemm(m1h, WdH + (size_t)l * FF * HH, nullptr, x, nullptr, M, HH, FF, 1, 0, 0);
    }

    rmsnorm_h_kernel<<<M, 256>>>(x, finln, xnh);
    build_xc_kernel<<<BB * SS, 256>>>(xnh, tvec, xch);

    const int BS = BB * SS;
    launch_hgemm(xch, rw1H, rate_b1, hr, nullptr, BS, TDIM, HH + TDIM, 0, 1, 0);
    rate2_kernel<<<BS, 128>>>(hr, rate_w2, rate_b2, pad, out);

    const size_t INS_OFF = (size_t)BS * 3;
    const size_t SUB_OFF = INS_OFF + (size_t)BS * VV;

    launch_hgemm(xch, iw1H, ins_b1, nullptr, h1h, BS, HH, HH + TDIM, 0, 1, 1);
    launch_hgemm(h1h, iw2H, ins_b2, out + INS_OFF, nullptr, BS, VV, HH, 0, 0, 0);
    softmaxV_kernel<<<BS, 256>>>(out + INS_OFF, pad);

    launch_hgemm(xch, sw1H, sub_b1, nullptr, h1h, BS, HH, HH + TDIM, 0, 1, 1);
    launch_hgemm(h1h, sw2H, sub_b2, out + SUB_OFF, nullptr, BS, VV, HH, 0, 0, 0);
    softmaxV_kernel<<<BS, 256>>>(out + SUB_OFF, pad);
}